// round 2
// baseline (speedup 1.0000x reference)
#include <cuda_runtime.h>
#include <math.h>

#define B_   8
#define S_   1024
#define D_   1024
#define H_   16
#define DK_  64
#define M_   (B_*S_)          // 8192 rows
#define NBUCK 32
#define NDELTA (2*S_-1)       // 2047

// ---------------- scratch (device globals: no cudaMalloc allowed) ------------
__device__ float g_q  [(size_t)M_*D_];
__device__ float g_k  [(size_t)M_*D_];
__device__ float g_v  [(size_t)M_*D_];
__device__ float g_ctx[(size_t)M_*D_];
__device__ float g_bias[H_*NDELTA];   // [h][delta+1023]

// ---------------- bias table -------------------------------------------------
// T5 bidirectional bucket. Boundary values n = 2^p (p>=3) give EXACT integer
// results in f32 with correctly-rounded logf; to be robust against 1-ulp logf
// differences vs XLA, powers of two are computed exactly: val = 2*(p-3).
// Non-boundary n have >=3e-4 distance to an integer (f32 error ~1e-6): safe.
__global__ void bias_kernel(const float* __restrict__ rel_emb) {
    int idx = blockIdx.x * blockDim.x + threadIdx.x;
    if (idx >= NDELTA) return;
    int delta = idx - (S_ - 1);      // k - q
    int n = -delta;
    int ret = (n < 0) ? (NBUCK / 2) : 0;
    n = (n < 0) ? -n : n;
    const int max_exact = NBUCK / 4; // 8
    int bv;
    if (n < max_exact) {
        bv = n;
    } else {
        int t;
        if ((n & (n - 1)) == 0) {           // n is a power of two (n >= 8)
            int p = 31 - __clz(n);
            t = 2 * (p - 3);                // exact boundary value
        } else {
            t = (int)((logf((float)n / 8.0f) / logf(16.0f)) * 8.0f);
        }
        bv = max_exact + t;
        if (bv > NBUCK / 2 - 1) bv = NBUCK / 2 - 1;
    }
    int bucket = ret + bv;
    #pragma unroll
    for (int h = 0; h < H_; h++)
        g_bias[h * NDELTA + idx] = rel_emb[bucket * H_ + h];
}

// ---------------- fp32 SGEMM: 128x128x16 tiles, 256 threads, 8x8 microtile ---
#define BM 128
#define BN 128
#define BKK 16

__global__ __launch_bounds__(256)
void sgemm128(const float* __restrict__ A, const float* __restrict__ B,
              float* __restrict__ C, int M, int N, int K) {
    __shared__ float As[2][BKK][BM + 4];   // +4 pad: kill transpose-store conflicts
    __shared__ float Bs[2][BKK][BN];

    const int tid  = threadIdx.x;
    const int tx   = tid & 15;
    const int ty   = tid >> 4;
    const int row0 = blockIdx.y * BM;
    const int col0 = blockIdx.x * BN;

    float acc[8][8];
    #pragma unroll
    for (int i = 0; i < 8; i++)
        #pragma unroll
        for (int j = 0; j < 8; j++) acc[i][j] = 0.f;

    float4 aR[2], bR[2];
    const int idx0 = tid * 2;

    auto fetch = [&](int kt) {
        #pragma unroll
        for (int i = 0; i < 2; i++) {
            int idx = idx0 + i;
            int ar  = idx >> 2;            // 0..127
            int ac  = (idx & 3) << 2;      // 0,4,8,12
            aR[i] = *(const float4*)(A + (size_t)(row0 + ar) * K + kt + ac);
            int br  = idx >> 5;            // 0..15
            int bc  = (idx & 31) << 2;     // 0..124
            bR[i] = *(const float4*)(B + (size_t)(kt + br) * N + col0 + bc);
        }
    };
    auto stash = [&](int buf) {
        #pragma unroll
        for (int i = 0; i < 2; i++) {
            int idx = idx0 + i;
            int ar  = idx >> 2;
            int ac  = (idx & 3) << 2;
            As[buf][ac + 0][ar] = aR[i].x;
            As[buf][ac + 1][ar] = aR[i].y;
            As[buf][ac + 2][ar] = aR[i].z;
            As[buf][ac + 3][ar] = aR[i].w;
            int br  = idx >> 5;
            int bc  = (idx & 31) << 2;
            *(float4*)&Bs[buf][br][bc] = bR[i];
        }
    };

    fetch(0);
    stash(0);
    __syncthreads();

    int buf = 0;
    for (int kt = 0; kt < K; kt += BKK) {
        int ktn = kt + BKK;
        if (ktn < K) fetch(ktn);
        #pragma unroll
        for (int kk = 0; kk < BKK; kk++) {
            float a[8], bb[8];
            #pragma unroll
            for (int i = 0; i < 8; i++) a[i]  = As[buf][kk][ty * 8 + i];
            #pragma unroll
            for (int j = 0; j < 8; j++) bb[j] = Bs[buf][kk][tx * 8 + j];
            #pragma unroll
            for (int i = 0; i < 8; i++)
                #pragma unroll
                for (int j = 0; j < 8; j++)
                    acc[i][j] += a[i] * bb[j];
        }
        if (ktn < K) stash(buf ^ 1);
        __syncthreads();
        buf ^= 1;
    }

    #pragma unroll
    for (int i = 0; i < 8; i++) {
        float* crow = C + (size_t)(row0 + ty * 8 + i) * N + col0 + tx * 8;
        *(float4*)crow       = make_float4(acc[i][0], acc[i][1], acc[i][2], acc[i][3]);
        *((float4*)crow + 1) = make_float4(acc[i][4], acc[i][5], acc[i][6], acc[i][7]);
    }
}

// ---------------- flash attention: CTA = (q-tile 64, head, batch) ------------
#define BQ  64
#define BKT 64

__global__ __launch_bounds__(BQ)
void attn_kernel(const float* __restrict__ Q, const float* __restrict__ Kg,
                 const float* __restrict__ Vg, float* __restrict__ ctx) {
    __shared__ float Ks[BKT][DK_];
    __shared__ float Vs[BKT][DK_];
    __shared__ float bias_s[BQ + BKT - 1];   // 127 deltas for this (q-tile, k-tile)

    const int qt = blockIdx.x;
    const int h  = blockIdx.y;
    const int b  = blockIdx.z;
    const int ti = threadIdx.x;              // one q row per thread
    const int qi = qt * BQ + ti;

    const float* qptr = Q + (size_t)(b * S_ + qi) * D_ + h * DK_;
    float4 qreg[DK_ / 4];
    #pragma unroll
    for (int i = 0; i < DK_ / 4; i++) qreg[i] = ((const float4*)qptr)[i];

    float m = -INFINITY, l = 0.f;
    float4 o[DK_ / 4];
    #pragma unroll
    for (int i = 0; i < DK_ / 4; i++) o[i] = make_float4(0.f, 0.f, 0.f, 0.f);

    // bias_s[j] = g_bias[h][ (k0 - qt*BQ) + (j-63) + 1023 ]
    const int biasBase = h * NDELTA - qt * BQ + 960;

    for (int k0 = 0; k0 < S_; k0 += BKT) {
        const float* kptr = Kg + (size_t)(b * S_ + k0 + ti) * D_ + h * DK_;
        const float* vptr = Vg + (size_t)(b * S_ + k0 + ti) * D_ + h * DK_;
        #pragma unroll
        for (int i = 0; i < DK_ / 4; i++) ((float4*)Ks[ti])[i] = ((const float4*)kptr)[i];
        #pragma unroll
        for (int i = 0; i < DK_ / 4; i++) ((float4*)Vs[ti])[i] = ((const float4*)vptr)[i];
        for (int j = ti; j < BQ + BKT - 1; j += BQ)
            bias_s[j] = g_bias[biasBase + k0 + j];
        __syncthreads();

        float s[BKT];
        float tmax = -INFINITY;
        #pragma unroll 4
        for (int kk = 0; kk < BKT; kk++) {
            const float4* kr = (const float4*)Ks[kk];   // broadcast across warp
            float a0 = 0.f, a1 = 0.f, a2 = 0.f, a3 = 0.f;
            #pragma unroll
            for (int i = 0; i < DK_ / 4; i++) {
                float4 kv = kr[i];
                a0 += qreg[i].x * kv.x;
                a1 += qreg[i].y * kv.y;
                a2 += qreg[i].z * kv.z;
                a3 += qreg[i].w * kv.w;
            }
            float sv = (a0 + a1) + (a2 + a3) + bias_s[kk - ti + 63];
            s[kk] = sv;
            tmax = fmaxf(tmax, sv);
        }

        float mn   = fmaxf(m, tmax);
        float corr = __expf(m - mn);
        l *= corr;
        #pragma unroll
        for (int i = 0; i < DK_ / 4; i++) {
            o[i].x *= corr; o[i].y *= corr; o[i].z *= corr; o[i].w *= corr;
        }

        #pragma unroll 4
        for (int kk = 0; kk < BKT; kk++) {
            float p = __expf(s[kk] - mn);
            l += p;
            const float4* vr = (const float4*)Vs[kk];
            #pragma unroll
            for (int i = 0; i < DK_ / 4; i++) {
                float4 vv = vr[i];
                o[i].x += p * vv.x; o[i].y += p * vv.y;
                o[i].z += p * vv.z; o[i].w += p * vv.w;
            }
        }
        m = mn;
        __syncthreads();
    }

    float inv = 1.f / l;
    float* optr = ctx + (size_t)(b * S_ + qi) * D_ + h * DK_;
    #pragma unroll
    for (int i = 0; i < DK_ / 4; i++) {
        float4 ov = o[i];
        ((float4*)optr)[i] = make_float4(ov.x * inv, ov.y * inv, ov.z * inv, ov.w * inv);
    }
}

// ---------------- launch -----------------------------------------------------
extern "C" void kernel_launch(void* const* d_in, const int* in_sizes, int n_in,
                              void* d_out, int out_size) {
    const float* x   = (const float*)d_in[0];
    const float* Wq  = (const float*)d_in[1];
    const float* Wk  = (const float*)d_in[2];
    const float* Wv  = (const float*)d_in[3];
    const float* Wo  = (const float*)d_in[4];
    const float* rel = (const float*)d_in[5];
    float* out = (float*)d_out;

    float *pq, *pk, *pv, *pctx;
    cudaGetSymbolAddress((void**)&pq,   g_q);
    cudaGetSymbolAddress((void**)&pk,   g_k);
    cudaGetSymbolAddress((void**)&pv,   g_v);
    cudaGetSymbolAddress((void**)&pctx, g_ctx);

    bias_kernel<<<(NDELTA + 127) / 128, 128>>>(rel);

    dim3 gg(D_ / BN, M_ / BM);   // (8, 64)
    sgemm128<<<gg, 256>>>(x, Wq, pq, M_, D_, D_);
    sgemm128<<<gg, 256>>>(x, Wk, pk, M_, D_, D_);
    sgemm128<<<gg, 256>>>(x, Wv, pv, M_, D_, D_);

    dim3 ga(S_ / BQ, H_, B_);    // (16, 16, 8)
    attn_kernel<<<ga, BQ>>>(pq, pk, pv, pctx);

    sgemm128<<<gg, 256>>>(pctx, Wo, out, M_, D_, D_);
}

// round 5
// speedup vs baseline: 1.8416x; 1.8416x over previous
#include <cuda_runtime.h>
#include <cuda_bf16.h>
#include <math.h>
#include <stdint.h>

#define B_   8
#define S_   1024
#define D_   1024
#define H_   16
#define DK_  64
#define M_   (B_*S_)          // 8192 rows
#define NBUCK 32
#define NDELTA (2*S_-1)       // 2047

// ---------------- scratch (device globals: no cudaMalloc allowed) ------------
__device__ float g_q  [(size_t)M_*D_];
__device__ float g_k  [(size_t)M_*D_];
__device__ float g_v  [(size_t)M_*D_];
__device__ float g_ctx[(size_t)M_*D_];
__device__ float g_bias[H_*NDELTA];   // [h][delta+1023]
// bf16 split buffers (hi + lo residual)
__device__ __nv_bfloat16 g_xh[(size_t)M_*D_], g_xl[(size_t)M_*D_];
__device__ __nv_bfloat16 g_ch[(size_t)M_*D_], g_cl[(size_t)M_*D_];
__device__ __nv_bfloat16 g_wh[4][(size_t)D_*D_], g_wl[4][(size_t)D_*D_];  // transposed [n][k]

// ============================ PTX helpers (baseline ISA only) ================
__device__ __forceinline__ uint32_t smem_u32(const void* p) {
    uint32_t a;
    asm("{ .reg .u64 t; cvta.to.shared.u64 t, %1; cvt.u32.u64 %0, t; }" : "=r"(a) : "l"(p));
    return a;
}
__device__ __forceinline__ void cp_async16(uint32_t dst, const void* src) {
    asm volatile("cp.async.cg.shared.global [%0], [%1], 16;" :: "r"(dst), "l"(src));
}
__device__ __forceinline__ void cp_commit() {
    asm volatile("cp.async.commit_group;" ::: "memory");
}
template <int N>
__device__ __forceinline__ void cp_wait() {
    asm volatile("cp.async.wait_group %0;" :: "n"(N) : "memory");
}
__device__ __forceinline__ void ldsm4(uint32_t* r, uint32_t addr) {
    asm volatile("ldmatrix.sync.aligned.m8n8.x4.shared.b16 {%0,%1,%2,%3}, [%4];"
                 : "=r"(r[0]), "=r"(r[1]), "=r"(r[2]), "=r"(r[3]) : "r"(addr));
}
__device__ __forceinline__ void mma16816(float* d, const uint32_t* a, const uint32_t* b) {
    asm volatile(
        "mma.sync.aligned.m16n8k16.row.col.f32.bf16.bf16.f32 "
        "{%0,%1,%2,%3}, {%4,%5,%6,%7}, {%8,%9}, {%0,%1,%2,%3};"
        : "+f"(d[0]), "+f"(d[1]), "+f"(d[2]), "+f"(d[3])
        : "r"(a[0]), "r"(a[1]), "r"(a[2]), "r"(a[3]), "r"(b[0]), "r"(b[1]));
}
__device__ __forceinline__ uint32_t sw128(uint32_t b) { return b ^ ((b >> 3) & 0x70); }

// ---------------- bias table -------------------------------------------------
__global__ void bias_kernel(const float* __restrict__ rel_emb) {
    int idx = blockIdx.x * blockDim.x + threadIdx.x;
    if (idx >= NDELTA) return;
    int delta = idx - (S_ - 1);      // k - q
    int n = -delta;
    int ret = (n < 0) ? (NBUCK / 2) : 0;
    n = (n < 0) ? -n : n;
    const int max_exact = NBUCK / 4; // 8
    int bv;
    if (n < max_exact) {
        bv = n;
    } else {
        int t;
        if ((n & (n - 1)) == 0) {           // power of two: exact boundary value
            int p = 31 - __clz(n);
            t = 2 * (p - 3);
        } else {
            t = (int)((logf((float)n / 8.0f) / logf(16.0f)) * 8.0f);
        }
        bv = max_exact + t;
        if (bv > NBUCK / 2 - 1) bv = NBUCK / 2 - 1;
    }
    int bucket = ret + bv;
    #pragma unroll
    for (int h = 0; h < H_; h++)
        g_bias[h * NDELTA + idx] = rel_emb[bucket * H_ + h];
}

// ---------------- bf16 split kernels -----------------------------------------
__global__ void split_act(const float4* __restrict__ src,
                          __nv_bfloat16* __restrict__ hi,
                          __nv_bfloat16* __restrict__ lo) {
    size_t i = (size_t)blockIdx.x * blockDim.x + threadIdx.x;
    float4 v = src[i];
    float vv[4] = {v.x, v.y, v.z, v.w};
    __nv_bfloat16 h[4], l[4];
    #pragma unroll
    for (int j = 0; j < 4; j++) {
        h[j] = __float2bfloat16(vv[j]);
        l[j] = __float2bfloat16(vv[j] - __bfloat162float(h[j]));
    }
    __nv_bfloat162* H = (__nv_bfloat162*)hi;
    __nv_bfloat162* L = (__nv_bfloat162*)lo;
    H[2*i]   = __nv_bfloat162(h[0], h[1]);
    H[2*i+1] = __nv_bfloat162(h[2], h[3]);
    L[2*i]   = __nv_bfloat162(l[0], l[1]);
    L[2*i+1] = __nv_bfloat162(l[2], l[3]);
}

// W [K][N] -> Wt [N][K] split into hi/lo
__global__ void split_wT(const float* __restrict__ W,
                         __nv_bfloat16* __restrict__ Th,
                         __nv_bfloat16* __restrict__ Tl) {
    __shared__ float t[32][33];
    const int n0 = blockIdx.x * 32, k0 = blockIdx.y * 32;
    for (int r = threadIdx.y; r < 32; r += 8)
        t[r][threadIdx.x] = W[(size_t)(k0 + r) * D_ + n0 + threadIdx.x];
    __syncthreads();
    for (int r = threadIdx.y; r < 32; r += 8) {
        float v = t[threadIdx.x][r];          // = W[k0+tx][n0+r]
        __nv_bfloat16 h = __float2bfloat16(v);
        size_t o = (size_t)(n0 + r) * D_ + k0 + threadIdx.x;
        Th[o] = h;
        Tl[o] = __float2bfloat16(v - __bfloat162float(h));
    }
}

// ---------------- HMMA bf16x3 GEMM: C[M,N] = A[M,K] * Bt[N,K]^T --------------
// 128x128 CTA tile, 8 warps 2(m)x4(n), warp tile 64x32, m16n8k16 atoms.
// K-chunks of 64 (128B SW128 rows), cp.async double buffered.
#define GM 128
#define GN 128
#define GKC 64
#define NCHUNK (D_ / GKC)             // 16
#define TILE_B (128*128)              // bytes per bf16 tile (128 rows x 128B)
#define GSMEM  (2*4*TILE_B)           // 131072

__global__ void __launch_bounds__(256, 1)
gemm_bf16x3(const __nv_bfloat16* __restrict__ Ah, const __nv_bfloat16* __restrict__ Al,
            const __nv_bfloat16* __restrict__ Bh, const __nv_bfloat16* __restrict__ Bl,
            float* __restrict__ C) {
    extern __shared__ char dsm[];
    const uint32_t smb = smem_u32(dsm);

    const int tid    = threadIdx.x;
    const int lane   = tid & 31;
    const int wid    = tid >> 5;
    const int warp_m = wid & 1;       // 0..1 (64 rows each)
    const int warp_n = wid >> 1;      // 0..3 (32 cols each)
    const int m0 = blockIdx.y * GM, n0 = blockIdx.x * GN;

    float acc[4][4][4];
    #pragma unroll
    for (int i = 0; i < 4; i++)
        #pragma unroll
        for (int j = 0; j < 4; j++)
            #pragma unroll
            for (int k = 0; k < 4; k++) acc[i][j][k] = 0.f;

    // ---- prefetch helper (16 float4 per thread per chunk) ----
    auto prefetch = [&](int ch) {
        const int kc0 = ch * GKC;
        const uint32_t db = smb + (uint32_t)(ch & 1) * (4 * TILE_B);
        #pragma unroll
        for (int j = 0; j < 4; j++) {
            int ci  = tid + j * 256;        // 0..1023
            int row = ci >> 3;              // 0..127
            int f4  = ci & 7;               // 0..7
            uint32_t so = sw128((uint32_t)(row * 128 + f4 * 16));
            size_t gaA = (size_t)(m0 + row) * D_ + kc0 + f4 * 8;
            size_t gaB = (size_t)(n0 + row) * D_ + kc0 + f4 * 8;
            cp_async16(db + 0*TILE_B + so, Ah + gaA);
            cp_async16(db + 1*TILE_B + so, Al + gaA);
            cp_async16(db + 2*TILE_B + so, Bh + gaB);
            cp_async16(db + 3*TILE_B + so, Bl + gaB);
        }
    };

    // ---- per-thread ldmatrix address components ----
    // A (x4): thread t -> row m0w + t%16, kbyte (t/16)*16
    const int aRow = warp_m * 64 + (lane & 15);
    const int aKb  = (lane >> 4) * 16;
    // B (x4, two n8 blocks): mat = t/8: n += (mat>>1)*8, kbyte (mat&1)*16
    const int bRow = warp_n * 32 + ((lane >> 4) << 3) + (lane & 7);
    const int bKb  = ((lane >> 3) & 1) * 16;

    prefetch(0);
    cp_commit();

    for (int ch = 0; ch < NCHUNK; ch++) {
        if (ch + 1 < NCHUNK) {
            prefetch(ch + 1);
            cp_commit();
            cp_wait<1>();
        } else {
            cp_wait<0>();
        }
        __syncthreads();

        const uint32_t base = smb + (uint32_t)(ch & 1) * (4 * TILE_B);
        const uint32_t aH = base, aL = base + TILE_B;
        const uint32_t bH = base + 2*TILE_B, bL = base + 3*TILE_B;

        #pragma unroll
        for (int ks = 0; ks < 4; ks++) {
            uint32_t a[4][4], bh[2][4], bl[2][4];
            #pragma unroll
            for (int mb = 0; mb < 4; mb++) {
                uint32_t off = sw128((uint32_t)((aRow + mb*16) * 128 + ks*32 + aKb));
                ldsm4(a[mb], aH + off);
            }
            #pragma unroll
            for (int nb2 = 0; nb2 < 2; nb2++) {
                uint32_t off = sw128((uint32_t)((bRow + nb2*16) * 128 + ks*32 + bKb));
                ldsm4(bh[nb2], bH + off);
                ldsm4(bl[nb2], bL + off);
            }
            // Ah*Bh and Ah*Bl
            #pragma unroll
            for (int mb = 0; mb < 4; mb++)
                #pragma unroll
                for (int nb = 0; nb < 4; nb++) {
                    mma16816(acc[mb][nb], a[mb], &bh[nb >> 1][(nb & 1) * 2]);
                    mma16816(acc[mb][nb], a[mb], &bl[nb >> 1][(nb & 1) * 2]);
                }
            // Al*Bh (reuse a regs)
            #pragma unroll
            for (int mb = 0; mb < 4; mb++) {
                uint32_t off = sw128((uint32_t)((aRow + mb*16) * 128 + ks*32 + aKb));
                ldsm4(a[mb], aL + off);
            }
            #pragma unroll
            for (int mb = 0; mb < 4; mb++)
                #pragma unroll
                for (int nb = 0; nb < 4; nb++)
                    mma16816(acc[mb][nb], a[mb], &bh[nb >> 1][(nb & 1) * 2]);
        }
        __syncthreads();
    }

    // ---- epilogue ----
    const int rowE = m0 + warp_m * 64 + (lane >> 2);
    const int colE = n0 + warp_n * 32 + (lane & 3) * 2;
    #pragma unroll
    for (int mb = 0; mb < 4; mb++)
        #pragma unroll
        for (int nb = 0; nb < 4; nb++) {
            float* p = C + (size_t)(rowE + mb*16) * D_ + colE + nb*8;
            *(float2*)p            = make_float2(acc[mb][nb][0], acc[mb][nb][1]);
            *(float2*)(p + 8*D_)   = make_float2(acc[mb][nb][2], acc[mb][nb][3]);
        }
}

// ---------------- flash attention (fp32 SIMT, unchanged) ---------------------
#define BQ  64
#define BKT 64

__global__ __launch_bounds__(BQ)
void attn_kernel(const float* __restrict__ Q, const float* __restrict__ Kg,
                 const float* __restrict__ Vg, float* __restrict__ ctx) {
    __shared__ float Ks[BKT][DK_];
    __shared__ float Vs[BKT][DK_];
    __shared__ float bias_s[BQ + BKT - 1];

    const int qt = blockIdx.x;
    const int h  = blockIdx.y;
    const int b  = blockIdx.z;
    const int ti = threadIdx.x;
    const int qi = qt * BQ + ti;

    const float* qptr = Q + (size_t)(b * S_ + qi) * D_ + h * DK_;
    float4 qreg[DK_ / 4];
    #pragma unroll
    for (int i = 0; i < DK_ / 4; i++) qreg[i] = ((const float4*)qptr)[i];

    float m = -INFINITY, l = 0.f;
    float4 o[DK_ / 4];
    #pragma unroll
    for (int i = 0; i < DK_ / 4; i++) o[i] = make_float4(0.f, 0.f, 0.f, 0.f);

    const int biasBase = h * NDELTA - qt * BQ + 960;

    for (int k0 = 0; k0 < S_; k0 += BKT) {
        const float* kptr = Kg + (size_t)(b * S_ + k0 + ti) * D_ + h * DK_;
        const float* vptr = Vg + (size_t)(b * S_ + k0 + ti) * D_ + h * DK_;
        #pragma unroll
        for (int i = 0; i < DK_ / 4; i++) ((float4*)Ks[ti])[i] = ((const float4*)kptr)[i];
        #pragma unroll
        for (int i = 0; i < DK_ / 4; i++) ((float4*)Vs[ti])[i] = ((const float4*)vptr)[i];
        for (int j = ti; j < BQ + BKT - 1; j += BQ)
            bias_s[j] = g_bias[biasBase + k0 + j];
        __syncthreads();

        float s[BKT];
        float tmax = -INFINITY;
        #pragma unroll 4
        for (int kk = 0; kk < BKT; kk++) {
            const float4* kr = (const float4*)Ks[kk];
            float a0 = 0.f, a1 = 0.f, a2 = 0.f, a3 = 0.f;
            #pragma unroll
            for (int i = 0; i < DK_ / 4; i++) {
                float4 kv = kr[i];
                a0 += qreg[i].x * kv.x;
                a1 += qreg[i].y * kv.y;
                a2 += qreg[i].z * kv.z;
                a3 += qreg[i].w * kv.w;
            }
            float sv = (a0 + a1) + (a2 + a3) + bias_s[kk - ti + 63];
            s[kk] = sv;
            tmax = fmaxf(tmax, sv);
        }

        float mn   = fmaxf(m, tmax);
        float corr = __expf(m - mn);
        l *= corr;
        #pragma unroll
        for (int i = 0; i < DK_ / 4; i++) {
            o[i].x *= corr; o[i].y *= corr; o[i].z *= corr; o[i].w *= corr;
        }

        #pragma unroll 4
        for (int kk = 0; kk < BKT; kk++) {
            float p = __expf(s[kk] - mn);
            l += p;
            const float4* vr = (const float4*)Vs[kk];
            #pragma unroll
            for (int i = 0; i < DK_ / 4; i++) {
                float4 vv = vr[i];
                o[i].x += p * vv.x; o[i].y += p * vv.y;
                o[i].z += p * vv.z; o[i].w += p * vv.w;
            }
        }
        m = mn;
        __syncthreads();
    }

    float inv = 1.f / l;
    float* optr = ctx + (size_t)(b * S_ + qi) * D_ + h * DK_;
    #pragma unroll
    for (int i = 0; i < DK_ / 4; i++) {
        float4 ov = o[i];
        ((float4*)optr)[i] = make_float4(ov.x * inv, ov.y * inv, ov.z * inv, ov.w * inv);
    }
}

// ---------------- launch -----------------------------------------------------
extern "C" void kernel_launch(void* const* d_in, const int* in_sizes, int n_in,
                              void* d_out, int out_size) {
    const float* x   = (const float*)d_in[0];
    const float* Wq  = (const float*)d_in[1];
    const float* Wk  = (const float*)d_in[2];
    const float* Wv  = (const float*)d_in[3];
    const float* Wo  = (const float*)d_in[4];
    const float* rel = (const float*)d_in[5];
    float* out = (float*)d_out;

    float *pq, *pk, *pv, *pctx;
    cudaGetSymbolAddress((void**)&pq,   g_q);
    cudaGetSymbolAddress((void**)&pk,   g_k);
    cudaGetSymbolAddress((void**)&pv,   g_v);
    cudaGetSymbolAddress((void**)&pctx, g_ctx);
    __nv_bfloat16 *xh, *xl, *chh, *cll, *wh, *wl;
    cudaGetSymbolAddress((void**)&xh, g_xh);
    cudaGetSymbolAddress((void**)&xl, g_xl);
    cudaGetSymbolAddress((void**)&chh, g_ch);
    cudaGetSymbolAddress((void**)&cll, g_cl);
    cudaGetSymbolAddress((void**)&wh, g_wh);
    cudaGetSymbolAddress((void**)&wl, g_wl);

    cudaFuncSetAttribute(gemm_bf16x3, cudaFuncAttributeMaxDynamicSharedMemorySize, GSMEM);

    bias_kernel<<<(NDELTA + 127) / 128, 128>>>(rel);

    split_act<<<(M_ * D_ / 4) / 256, 256>>>((const float4*)x, xh, xl);
    {
        dim3 gt(32, 32), bt(32, 8);
        const float* Ws[4] = {Wq, Wk, Wv, Wo};
        for (int i = 0; i < 4; i++)
            split_wT<<<gt, bt>>>(Ws[i], wh + (size_t)i * D_ * D_, wl + (size_t)i * D_ * D_);
    }

    dim3 gg(D_ / GN, M_ / GM);   // (8, 64)
    gemm_bf16x3<<<gg, 256, GSMEM>>>(xh, xl, wh + 0*(size_t)D_*D_, wl + 0*(size_t)D_*D_, pq);
    gemm_bf16x3<<<gg, 256, GSMEM>>>(xh, xl, wh + 1*(size_t)D_*D_, wl + 1*(size_t)D_*D_, pk);
    gemm_bf16x3<<<gg, 256, GSMEM>>>(xh, xl, wh + 2*(size_t)D_*D_, wl + 2*(size_t)D_*D_, pv);

    dim3 ga(S_ / BQ, H_, B_);    // (16, 16, 8)
    attn_kernel<<<ga, BQ>>>(pq, pk, pv, pctx);

    split_act<<<(M_ * D_ / 4) / 256, 256>>>((const float4*)pctx, chh, cll);
    gemm_bf16x3<<<gg, 256, GSMEM>>>(chh, cll, wh + 3*(size_t)D_*D_, wl + 3*(size_t)D_*D_, out);
}

// round 7
// speedup vs baseline: 4.7960x; 2.6042x over previous
#include <cuda_runtime.h>
#include <cuda_bf16.h>
#include <math.h>
#include <stdint.h>

#define B_   8
#define S_   1024
#define D_   1024
#define H_   16
#define DK_  64
#define M_   (B_*S_)          // 8192 rows
#define NBUCK 32
#define NDELTA (2*S_-1)       // 2047

// ---------------- scratch (device globals: no cudaMalloc allowed) ------------
__device__ float g_q  [(size_t)M_*D_];
__device__ float g_k  [(size_t)M_*D_];
__device__ float g_v  [(size_t)M_*D_];
__device__ float g_ctx[(size_t)M_*D_];
__device__ float g_bias[H_*NDELTA];   // [h][delta+1023]
// bf16 split buffers (hi + lo residual)
__device__ __nv_bfloat16 g_xh[(size_t)M_*D_], g_xl[(size_t)M_*D_];
__device__ __nv_bfloat16 g_ch[(size_t)M_*D_], g_cl[(size_t)M_*D_];
__device__ __nv_bfloat16 g_wh[4][(size_t)D_*D_], g_wl[4][(size_t)D_*D_];  // transposed [n][k]
// attention operands, head-major bf16 splits
__device__ __nv_bfloat16 g_aqh[(size_t)M_*D_], g_aql[(size_t)M_*D_];   // [b][h][s][dk]
__device__ __nv_bfloat16 g_akh[(size_t)M_*D_], g_akl[(size_t)M_*D_];   // [b][h][s][dk]
__device__ __nv_bfloat16 g_avh[(size_t)M_*D_], g_avl[(size_t)M_*D_];   // [b][h][dk][s] (transposed)

// ============================ PTX helpers (baseline ISA only) ================
__device__ __forceinline__ uint32_t smem_u32(const void* p) {
    uint32_t a;
    asm("{ .reg .u64 t; cvta.to.shared.u64 t, %1; cvt.u32.u64 %0, t; }" : "=r"(a) : "l"(p));
    return a;
}
__device__ __forceinline__ void cp_async16(uint32_t dst, const void* src) {
    asm volatile("cp.async.cg.shared.global [%0], [%1], 16;" :: "r"(dst), "l"(src));
}
__device__ __forceinline__ void cp_commit() {
    asm volatile("cp.async.commit_group;" ::: "memory");
}
template <int N>
__device__ __forceinline__ void cp_wait() {
    asm volatile("cp.async.wait_group %0;" :: "n"(N) : "memory");
}
__device__ __forceinline__ void ldsm4(uint32_t* r, uint32_t addr) {
    asm volatile("ldmatrix.sync.aligned.m8n8.x4.shared.b16 {%0,%1,%2,%3}, [%4];"
                 : "=r"(r[0]), "=r"(r[1]), "=r"(r[2]), "=r"(r[3]) : "r"(addr));
}
__device__ __forceinline__ void mma16816(float* d, const uint32_t* a, const uint32_t* b) {
    asm volatile(
        "mma.sync.aligned.m16n8k16.row.col.f32.bf16.bf16.f32 "
        "{%0,%1,%2,%3}, {%4,%5,%6,%7}, {%8,%9}, {%0,%1,%2,%3};"
        : "+f"(d[0]), "+f"(d[1]), "+f"(d[2]), "+f"(d[3])
        : "r"(a[0]), "r"(a[1]), "r"(a[2]), "r"(a[3]), "r"(b[0]), "r"(b[1]));
}
__device__ __forceinline__ uint32_t sw128(uint32_t b) { return b ^ ((b >> 3) & 0x70); }
// pack two floats into bf16x2 reg: low half = lo, high half = hi
__device__ __forceinline__ uint32_t pack_bf2(float lo, float hi) {
    uint32_t d;
    asm("cvt.rn.bf16x2.f32 %0, %1, %2;" : "=r"(d) : "f"(hi), "f"(lo));
    return d;
}

// ---------------- bias table -------------------------------------------------
__global__ void bias_kernel(const float* __restrict__ rel_emb) {
    int idx = blockIdx.x * blockDim.x + threadIdx.x;
    if (idx >= NDELTA) return;
    int delta = idx - (S_ - 1);      // k - q
    int n = -delta;
    int ret = (n < 0) ? (NBUCK / 2) : 0;
    n = (n < 0) ? -n : n;
    const int max_exact = NBUCK / 4; // 8
    int bv;
    if (n < max_exact) {
        bv = n;
    } else {
        int t;
        if ((n & (n - 1)) == 0) {           // power of two: exact boundary value
            int p = 31 - __clz(n);
            t = 2 * (p - 3);
        } else {
            t = (int)((logf((float)n / 8.0f) / logf(16.0f)) * 8.0f);
        }
        bv = max_exact + t;
        if (bv > NBUCK / 2 - 1) bv = NBUCK / 2 - 1;
    }
    int bucket = ret + bv;
    #pragma unroll
    for (int h = 0; h < H_; h++)
        g_bias[h * NDELTA + idx] = rel_emb[bucket * H_ + h];
}

// ---------------- bf16 split kernels -----------------------------------------
__global__ void split_act(const float4* __restrict__ src,
                          __nv_bfloat16* __restrict__ hi,
                          __nv_bfloat16* __restrict__ lo) {
    size_t i = (size_t)blockIdx.x * blockDim.x + threadIdx.x;
    float4 v = src[i];
    float vv[4] = {v.x, v.y, v.z, v.w};
    __nv_bfloat16 h[4], l[4];
    #pragma unroll
    for (int j = 0; j < 4; j++) {
        h[j] = __float2bfloat16(vv[j]);
        l[j] = __float2bfloat16(vv[j] - __bfloat162float(h[j]));
    }
    __nv_bfloat162* H = (__nv_bfloat162*)hi;
    __nv_bfloat162* L = (__nv_bfloat162*)lo;
    H[2*i]   = __nv_bfloat162(h[0], h[1]);
    H[2*i+1] = __nv_bfloat162(h[2], h[3]);
    L[2*i]   = __nv_bfloat162(l[0], l[1]);
    L[2*i+1] = __nv_bfloat162(l[2], l[3]);
}

// W [K][N] -> Wt [N][K] split into hi/lo
__global__ void split_wT(const float* __restrict__ W,
                         __nv_bfloat16* __restrict__ Th,
                         __nv_bfloat16* __restrict__ Tl) {
    __shared__ float t[32][33];
    const int n0 = blockIdx.x * 32, k0 = blockIdx.y * 32;
    for (int r = threadIdx.y; r < 32; r += 8)
        t[r][threadIdx.x] = W[(size_t)(k0 + r) * D_ + n0 + threadIdx.x];
    __syncthreads();
    for (int r = threadIdx.y; r < 32; r += 8) {
        float v = t[threadIdx.x][r];          // = W[k0+tx][n0+r]
        __nv_bfloat16 h = __float2bfloat16(v);
        size_t o = (size_t)(n0 + r) * D_ + k0 + threadIdx.x;
        Th[o] = h;
        Tl[o] = __float2bfloat16(v - __bfloat162float(h));
    }
}

// ---------------- attention prep: Q,K -> head-major bf16 splits --------------
__global__ void prep_qk(const float* __restrict__ Q, const float* __restrict__ K,
                        __nv_bfloat16* __restrict__ qh, __nv_bfloat16* __restrict__ ql,
                        __nv_bfloat16* __restrict__ kh, __nv_bfloat16* __restrict__ kl) {
    int idx = blockIdx.x * blockDim.x + threadIdx.x;     // over M_ * 256 f4 groups
    int r   = idx >> 8;            // row (b*S+s)
    int c4  = idx & 255;
    int h   = c4 >> 4;
    int d4  = c4 & 15;
    int b = r >> 10, s = r & 1023;
    size_t src = (size_t)r * D_ + h * DK_ + d4 * 4;
    size_t dst = ((size_t)(b * H_ + h) * S_ + s) * DK_ + d4 * 4;
    #pragma unroll
    for (int which = 0; which < 2; which++) {
        const float* P = which ? K : Q;
        __nv_bfloat16* PH = which ? kh : qh;
        __nv_bfloat16* PL = which ? kl : ql;
        float4 v = *(const float4*)(P + src);
        float vv[4] = {v.x, v.y, v.z, v.w};
        __nv_bfloat16 hh[4], ll[4];
        #pragma unroll
        for (int j = 0; j < 4; j++) {
            hh[j] = __float2bfloat16(vv[j]);
            ll[j] = __float2bfloat16(vv[j] - __bfloat162float(hh[j]));
        }
        *(__nv_bfloat162*)(PH + dst)     = __nv_bfloat162(hh[0], hh[1]);
        *(__nv_bfloat162*)(PH + dst + 2) = __nv_bfloat162(hh[2], hh[3]);
        *(__nv_bfloat162*)(PL + dst)     = __nv_bfloat162(ll[0], ll[1]);
        *(__nv_bfloat162*)(PL + dst + 2) = __nv_bfloat162(ll[2], ll[3]);
    }
}

// ---------------- attention prep: V -> transposed head-major bf16 splits -----
__global__ void prep_vT(const float* __restrict__ V,
                        __nv_bfloat16* __restrict__ vh, __nv_bfloat16* __restrict__ vl) {
    __shared__ float tl_[32][33];
    const int bh = blockIdx.z;             // b*H + h
    const int s0 = blockIdx.x * 32;
    const int d0 = blockIdx.y * 32;
    const int b = bh >> 4, h = bh & 15;
    for (int r = threadIdx.y; r < 32; r += 8)
        tl_[r][threadIdx.x] = V[(size_t)(b * S_ + s0 + r) * D_ + h * DK_ + d0 + threadIdx.x];
    __syncthreads();
    for (int r = threadIdx.y; r < 32; r += 8) {
        float v = tl_[threadIdx.x][r];     // = V[s0+tx][d0+r]
        __nv_bfloat16 hh = __float2bfloat16(v);
        size_t o = ((size_t)bh * DK_ + d0 + r) * S_ + s0 + threadIdx.x;
        vh[o] = hh;
        vl[o] = __float2bfloat16(v - __bfloat162float(hh));
    }
}

// ---------------- HMMA bf16x3 GEMM: C[M,N] = A[M,K] * Bt[N,K]^T --------------
#define GM 128
#define GN 128
#define GKC 64
#define NCHUNK (D_ / GKC)             // 16
#define TILE_B (128*128)              // bytes per bf16 tile (128 rows x 128B)
#define GSMEM  (2*4*TILE_B)           // 131072

__global__ void __launch_bounds__(256, 1)
gemm_bf16x3(const __nv_bfloat16* __restrict__ Ah, const __nv_bfloat16* __restrict__ Al,
            const __nv_bfloat16* __restrict__ Bh, const __nv_bfloat16* __restrict__ Bl,
            float* __restrict__ C) {
    extern __shared__ char dsm[];
    const uint32_t smb = smem_u32(dsm);

    const int tid    = threadIdx.x;
    const int lane   = tid & 31;
    const int wid    = tid >> 5;
    const int warp_m = wid & 1;
    const int warp_n = wid >> 1;
    const int m0 = blockIdx.y * GM, n0 = blockIdx.x * GN;

    float acc[4][4][4];
    #pragma unroll
    for (int i = 0; i < 4; i++)
        #pragma unroll
        for (int j = 0; j < 4; j++)
            #pragma unroll
            for (int k = 0; k < 4; k++) acc[i][j][k] = 0.f;

    auto prefetch = [&](int ch) {
        const int kc0 = ch * GKC;
        const uint32_t db = smb + (uint32_t)(ch & 1) * (4 * TILE_B);
        #pragma unroll
        for (int j = 0; j < 4; j++) {
            int ci  = tid + j * 256;
            int row = ci >> 3;
            int f4  = ci & 7;
            uint32_t so = sw128((uint32_t)(row * 128 + f4 * 16));
            size_t gaA = (size_t)(m0 + row) * D_ + kc0 + f4 * 8;
            size_t gaB = (size_t)(n0 + row) * D_ + kc0 + f4 * 8;
            cp_async16(db + 0*TILE_B + so, Ah + gaA);
            cp_async16(db + 1*TILE_B + so, Al + gaA);
            cp_async16(db + 2*TILE_B + so, Bh + gaB);
            cp_async16(db + 3*TILE_B + so, Bl + gaB);
        }
    };

    const int aRow = warp_m * 64 + (lane & 15);
    const int aKb  = (lane >> 4) * 16;
    const int bRow = warp_n * 32 + ((lane >> 4) << 3) + (lane & 7);
    const int bKb  = ((lane >> 3) & 1) * 16;

    prefetch(0);
    cp_commit();

    for (int ch = 0; ch < NCHUNK; ch++) {
        if (ch + 1 < NCHUNK) {
            prefetch(ch + 1);
            cp_commit();
            cp_wait<1>();
        } else {
            cp_wait<0>();
        }
        __syncthreads();

        const uint32_t base = smb + (uint32_t)(ch & 1) * (4 * TILE_B);
        const uint32_t aH = base, aL = base + TILE_B;
        const uint32_t bH = base + 2*TILE_B, bL = base + 3*TILE_B;

        #pragma unroll
        for (int ks = 0; ks < 4; ks++) {
            uint32_t a[4][4], bh[2][4], bl[2][4];
            #pragma unroll
            for (int mb = 0; mb < 4; mb++) {
                uint32_t off = sw128((uint32_t)((aRow + mb*16) * 128 + ks*32 + aKb));
                ldsm4(a[mb], aH + off);
            }
            #pragma unroll
            for (int nb2 = 0; nb2 < 2; nb2++) {
                uint32_t off = sw128((uint32_t)((bRow + nb2*16) * 128 + ks*32 + bKb));
                ldsm4(bh[nb2], bH + off);
                ldsm4(bl[nb2], bL + off);
            }
            #pragma unroll
            for (int mb = 0; mb < 4; mb++)
                #pragma unroll
                for (int nb = 0; nb < 4; nb++) {
                    mma16816(acc[mb][nb], a[mb], &bh[nb >> 1][(nb & 1) * 2]);
                    mma16816(acc[mb][nb], a[mb], &bl[nb >> 1][(nb & 1) * 2]);
                }
            #pragma unroll
            for (int mb = 0; mb < 4; mb++) {
                uint32_t off = sw128((uint32_t)((aRow + mb*16) * 128 + ks*32 + aKb));
                ldsm4(a[mb], aL + off);
            }
            #pragma unroll
            for (int mb = 0; mb < 4; mb++)
                #pragma unroll
                for (int nb = 0; nb < 4; nb++)
                    mma16816(acc[mb][nb], a[mb], &bh[nb >> 1][(nb & 1) * 2]);
        }
        __syncthreads();
    }

    const int rowE = m0 + warp_m * 64 + (lane >> 2);
    const int colE = n0 + warp_n * 32 + (lane & 3) * 2;
    #pragma unroll
    for (int mb = 0; mb < 4; mb++)
        #pragma unroll
        for (int nb = 0; nb < 4; nb++) {
            float* p = C + (size_t)(rowE + mb*16) * D_ + colE + nb*8;
            *(float2*)p            = make_float2(acc[mb][nb][0], acc[mb][nb][1]);
            *(float2*)(p + 8*D_)   = make_float2(acc[mb][nb][2], acc[mb][nb][3]);
        }
}

// ---------------- HMMA flash attention ---------------------------------------
// CTA: (q-tile 128, h, b). 8 warps x 16 q rows. k-tiles of 64, double buffered.
// scores = Qh*Kh + Qh*Kl + Ql*Kh (+bias), online softmax, PV = Ph*Vh+Ph*Vl+Pl*Vh.
#define AQ 128
#define AK 64
#define A_QTILE 16384                 // 128 rows x 128B
#define A_KVT    8192                 // 64 rows x 128B
#define A_BUFSZ (4*A_KVT)             // Kh,Kl,Vth,Vtl
#define A_SMQH  0
#define A_SMQL  16384
#define A_SMBUF 32768
#define A_SMBIAS (32768 + 2*A_BUFSZ)  // 98304
#define A_SMEM  (A_SMBIAS + 2*192*4)  // 99840

__global__ void __launch_bounds__(256, 1)
attn_mma(const __nv_bfloat16* __restrict__ Qh, const __nv_bfloat16* __restrict__ Ql,
         const __nv_bfloat16* __restrict__ Kh, const __nv_bfloat16* __restrict__ Kl,
         const __nv_bfloat16* __restrict__ Vth, const __nv_bfloat16* __restrict__ Vtl,
         float* __restrict__ ctx) {
    extern __shared__ char dsm[];
    const uint32_t smb = smem_u32(dsm);
    float* bias_s = (float*)(dsm + A_SMBIAS);   // [2][192]

    const int tid  = threadIdx.x;
    const int lane = tid & 31;
    const int w    = tid >> 5;
    const int q0 = blockIdx.x * AQ;
    const int h  = blockIdx.y;
    const int b  = blockIdx.z;
    const int bh = b * H_ + h;

    // ldmatrix address components (identical pattern to validated GEMM)
    const int aRow = w * 16 + (lane & 15);
    const int aKb  = (lane >> 4) * 16;
    const int bRowB = ((lane >> 4) << 3) + (lane & 7);
    const int bKb   = ((lane >> 3) & 1) * 16;

    // ---- load Q tiles (q0..q0+127, 64 dk) ----
    #pragma unroll
    for (int j = 0; j < 4; j++) {
        int ci = tid + j * 256;          // 0..1023
        int row = ci >> 3, f4 = ci & 7;
        uint32_t so = sw128((uint32_t)(row * 128 + f4 * 16));
        size_t ga = ((size_t)bh * S_ + q0 + row) * DK_ + f4 * 8;
        cp_async16(smb + A_SMQH + so, Qh + ga);
        cp_async16(smb + A_SMQL + so, Ql + ga);
    }

    auto prefetch = [&](int it) {
        const int k0 = it * AK;
        const uint32_t db = smb + A_SMBUF + (uint32_t)(it & 1) * A_BUFSZ;
        #pragma unroll
        for (int j = 0; j < 2; j++) {
            int ci = tid + j * 256;      // 0..511
            int row = ci >> 3, f4 = ci & 7;
            uint32_t so = sw128((uint32_t)(row * 128 + f4 * 16));
            size_t gk = ((size_t)bh * S_ + k0 + row) * DK_ + f4 * 8;
            size_t gv = ((size_t)bh * DK_ + row) * S_ + k0 + f4 * 8;
            cp_async16(db + 0*A_KVT + so, Kh  + gk);
            cp_async16(db + 1*A_KVT + so, Kl  + gk);
            cp_async16(db + 2*A_KVT + so, Vth + gv);
            cp_async16(db + 3*A_KVT + so, Vtl + gv);
        }
    };
    auto stage_bias = [&](int it) {
        if (tid < 191)
            bias_s[(it & 1) * 192 + tid] =
                g_bias[h * NDELTA + it * AK - q0 + tid + 896];
    };

    prefetch(0);
    stage_bias(0);
    cp_commit();

    float m0r = -INFINITY, m1r = -INFINITY, l0 = 0.f, l1 = 0.f;
    float oa[8][4];
    #pragma unroll
    for (int i = 0; i < 8; i++)
        #pragma unroll
        for (int j = 0; j < 4; j++) oa[i][j] = 0.f;

    const int kcb = (lane & 3) * 2;
    const int rql = w * 16 + (lane >> 2);

    for (int it = 0; it < S_ / AK; it++) {
        if (it + 1 < S_ / AK) {
            prefetch(it + 1);
            stage_bias(it + 1);
            cp_commit();
            cp_wait<1>();
        } else {
            cp_wait<0>();
        }
        __syncthreads();

        const uint32_t base = smb + A_SMBUF + (uint32_t)(it & 1) * A_BUFSZ;
        const uint32_t kH = base, kL = base + A_KVT;
        const uint32_t vH = base + 2*A_KVT, vL = base + 3*A_KVT;
        const float* bp = bias_s + (it & 1) * 192;

        // ---- scores: 16q x 64k per warp ----
        float sa[8][4];
        #pragma unroll
        for (int i = 0; i < 8; i++)
            #pragma unroll
            for (int j = 0; j < 4; j++) sa[i][j] = 0.f;

        #pragma unroll
        for (int ks = 0; ks < 4; ks++) {
            uint32_t qh_f[4], ql_f[4];
            uint32_t qoff = sw128((uint32_t)(aRow * 128 + ks*32 + aKb));
            ldsm4(qh_f, smb + A_SMQH + qoff);
            ldsm4(ql_f, smb + A_SMQL + qoff);
            uint32_t khf[4][4], klf[4][4];
            #pragma unroll
            for (int nb2 = 0; nb2 < 4; nb2++) {
                uint32_t off = sw128((uint32_t)((bRowB + nb2*16) * 128 + ks*32 + bKb));
                ldsm4(khf[nb2], kH + off);
                ldsm4(klf[nb2], kL + off);
            }
            #pragma unroll
            for (int t = 0; t < 8; t++) {
                uint32_t* bhp = &khf[t >> 1][(t & 1) * 2];
                uint32_t* blp = &klf[t >> 1][(t & 1) * 2];
                mma16816(sa[t], qh_f, bhp);
                mma16816(sa[t], qh_f, blp);
                mma16816(sa[t], ql_f, bhp);
            }
        }

        // ---- bias + online softmax ----
        float mx0 = -INFINITY, mx1 = -INFINITY;
        #pragma unroll
        for (int t = 0; t < 8; t++) {
            int bi = t*8 + kcb - rql + 127;
            float s0 = sa[t][0] + bp[bi];
            float s1 = sa[t][1] + bp[bi + 1];
            float s2 = sa[t][2] + bp[bi - 8];
            float s3 = sa[t][3] + bp[bi - 7];
            sa[t][0] = s0; sa[t][1] = s1; sa[t][2] = s2; sa[t][3] = s3;
            mx0 = fmaxf(mx0, fmaxf(s0, s1));
            mx1 = fmaxf(mx1, fmaxf(s2, s3));
        }
        mx0 = fmaxf(mx0, __shfl_xor_sync(0xffffffffu, mx0, 1));
        mx0 = fmaxf(mx0, __shfl_xor_sync(0xffffffffu, mx0, 2));
        mx1 = fmaxf(mx1, __shfl_xor_sync(0xffffffffu, mx1, 1));
        mx1 = fmaxf(mx1, __shfl_xor_sync(0xffffffffu, mx1, 2));
        float mn0 = fmaxf(m0r, mx0), mn1 = fmaxf(m1r, mx1);
        float c0 = __expf(m0r - mn0), c1 = __expf(m1r - mn1);
        l0 *= c0; l1 *= c1;
        #pragma unroll
        for (int dt = 0; dt < 8; dt++) {
            oa[dt][0] *= c0; oa[dt][1] *= c0;
            oa[dt][2] *= c1; oa[dt][3] *= c1;
        }
        m0r = mn0; m1r = mn1;
        #pragma unroll
        for (int t = 0; t < 8; t++) {
            float p0 = __expf(sa[t][0] - mn0);
            float p1 = __expf(sa[t][1] - mn0);
            float p2 = __expf(sa[t][2] - mn1);
            float p3 = __expf(sa[t][3] - mn1);
            l0 += p0 + p1; l1 += p2 + p3;
            sa[t][0] = p0; sa[t][1] = p1; sa[t][2] = p2; sa[t][3] = p3;
        }

        // ---- PV: P[16x64] * Vt^T -> o[16x64] ----
        #pragma unroll
        for (int ks = 0; ks < 4; ks++) {
            const int t0 = 2*ks, t1 = 2*ks + 1;
            uint32_t pah[4], pal[4];
            #pragma unroll
            for (int half = 0; half < 2; half++) {
                const int tt = half ? t1 : t0;
                float p0 = sa[tt][0], p1 = sa[tt][1], p2 = sa[tt][2], p3 = sa[tt][3];
                float h0 = __bfloat162float(__float2bfloat16_rn(p0));
                float h1 = __bfloat162float(__float2bfloat16_rn(p1));
                float h2 = __bfloat162float(__float2bfloat16_rn(p2));
                float h3 = __bfloat162float(__float2bfloat16_rn(p3));
                pah[half*2 + 0] = pack_bf2(p0, p1);
                pah[half*2 + 1] = pack_bf2(p2, p3);
                pal[half*2 + 0] = pack_bf2(p0 - h0, p1 - h1);
                pal[half*2 + 1] = pack_bf2(p2 - h2, p3 - h3);
            }
            uint32_t vhf[4][4], vlf[4][4];
            #pragma unroll
            for (int nb2 = 0; nb2 < 4; nb2++) {
                uint32_t off = sw128((uint32_t)((bRowB + nb2*16) * 128 + ks*32 + bKb));
                ldsm4(vhf[nb2], vH + off);
                ldsm4(vlf[nb2], vL + off);
            }
            #pragma unroll
            for (int dt = 0; dt < 8; dt++) {
                uint32_t* b1 = &vhf[dt >> 1][(dt & 1) * 2];
                uint32_t* b2 = &vlf[dt >> 1][(dt & 1) * 2];
                mma16816(oa[dt], pah, b1);
                mma16816(oa[dt], pah, b2);
                mma16816(oa[dt], pal, b1);
            }
        }
        __syncthreads();
    }

    // ---- finalize ----
    l0 += __shfl_xor_sync(0xffffffffu, l0, 1);
    l0 += __shfl_xor_sync(0xffffffffu, l0, 2);
    l1 += __shfl_xor_sync(0xffffffffu, l1, 1);
    l1 += __shfl_xor_sync(0xffffffffu, l1, 2);
    float inv0 = 1.f / l0, inv1 = 1.f / l1;
    const int rowg = b * S_ + q0 + rql;
    #pragma unroll
    for (int dt = 0; dt < 8; dt++) {
        float* p = ctx + (size_t)rowg * D_ + h * DK_ + dt*8 + kcb;
        *(float2*)p          = make_float2(oa[dt][0] * inv0, oa[dt][1] * inv0);
        *(float2*)(p + 8*D_) = make_float2(oa[dt][2] * inv1, oa[dt][3] * inv1);
    }
}

// ---------------- launch -----------------------------------------------------
extern "C" void kernel_launch(void* const* d_in, const int* in_sizes, int n_in,
                              void* d_out, int out_size) {
    const float* x   = (const float*)d_in[0];
    const float* Wq  = (const float*)d_in[1];
    const float* Wk  = (const float*)d_in[2];
    const float* Wv  = (const float*)d_in[3];
    const float* Wo  = (const float*)d_in[4];
    const float* rel = (const float*)d_in[5];
    float* out = (float*)d_out;

    float *pq, *pk, *pv, *pctx;
    cudaGetSymbolAddress((void**)&pq,   g_q);
    cudaGetSymbolAddress((void**)&pk,   g_k);
    cudaGetSymbolAddress((void**)&pv,   g_v);
    cudaGetSymbolAddress((void**)&pctx, g_ctx);
    __nv_bfloat16 *xh, *xl, *chh, *cll, *wh, *wl;
    cudaGetSymbolAddress((void**)&xh, g_xh);
    cudaGetSymbolAddress((void**)&xl, g_xl);
    cudaGetSymbolAddress((void**)&chh, g_ch);
    cudaGetSymbolAddress((void**)&cll, g_cl);
    cudaGetSymbolAddress((void**)&wh, g_wh);
    cudaGetSymbolAddress((void**)&wl, g_wl);
    __nv_bfloat16 *aqh, *aql, *akh, *akl, *avh, *avl;
    cudaGetSymbolAddress((void**)&aqh, g_aqh);
    cudaGetSymbolAddress((void**)&aql, g_aql);
    cudaGetSymbolAddress((void**)&akh, g_akh);
    cudaGetSymbolAddress((void**)&akl, g_akl);
    cudaGetSymbolAddress((void**)&avh, g_avh);
    cudaGetSymbolAddress((void**)&avl, g_avl);

    cudaFuncSetAttribute(gemm_bf16x3, cudaFuncAttributeMaxDynamicSharedMemorySize, GSMEM);
    cudaFuncSetAttribute(attn_mma,    cudaFuncAttributeMaxDynamicSharedMemorySize, A_SMEM);

    bias_kernel<<<(NDELTA + 127) / 128, 128>>>(rel);

    split_act<<<(M_ * D_ / 4) / 256, 256>>>((const float4*)x, xh, xl);
    {
        dim3 gt(32, 32), bt(32, 8);
        const float* Ws[4] = {Wq, Wk, Wv, Wo};
        for (int i = 0; i < 4; i++)
            split_wT<<<gt, bt>>>(Ws[i], wh + (size_t)i * D_ * D_, wl + (size_t)i * D_ * D_);
    }

    dim3 gg(D_ / GN, M_ / GM);   // (8, 64)
    gemm_bf16x3<<<gg, 256, GSMEM>>>(xh, xl, wh + 0*(size_t)D_*D_, wl + 0*(size_t)D_*D_, pq);
    gemm_bf16x3<<<gg, 256, GSMEM>>>(xh, xl, wh + 1*(size_t)D_*D_, wl + 1*(size_t)D_*D_, pk);
    gemm_bf16x3<<<gg, 256, GSMEM>>>(xh, xl, wh + 2*(size_t)D_*D_, wl + 2*(size_t)D_*D_, pv);

    prep_qk<<<(M_ * 256) / 256, 256>>>(pq, pk, aqh, aql, akh, akl);
    {
        dim3 gt(S_ / 32, DK_ / 32, B_ * H_), bt(32, 8);
        prep_vT<<<gt, bt>>>(pv, avh, avl);
    }

    dim3 ga(S_ / AQ, H_, B_);    // (8, 16, 8)
    attn_mma<<<ga, 256, A_SMEM>>>(aqh, aql, akh, akl, avh, avl, pctx);

    split_act<<<(M_ * D_ / 4) / 256, 256>>>((const float4*)pctx, chh, cll);
    gemm_bf16x3<<<gg, 256, GSMEM>>>(chh, cll, wh + 3*(size_t)D_*D_, wl + 3*(size_t)D_*D_, out);
}

// round 8
// speedup vs baseline: 5.1478x; 1.0734x over previous
#include <cuda_runtime.h>
#include <cuda_bf16.h>
#include <math.h>
#include <stdint.h>

#define B_   8
#define S_   1024
#define D_   1024
#define H_   16
#define DK_  64
#define M_   (B_*S_)          // 8192 rows
#define NBUCK 32
#define NDELTA (2*S_-1)       // 2047

// ---------------- scratch (device globals: no cudaMalloc allowed) ------------
__device__ float g_bias[H_*NDELTA];   // [h][delta+1023]
// bf16 split buffers (hi + lo residual)
__device__ __nv_bfloat16 g_xh[(size_t)M_*D_], g_xl[(size_t)M_*D_];
__device__ __nv_bfloat16 g_ch[(size_t)M_*D_], g_cl[(size_t)M_*D_];   // ctx split [m][h*dk]
__device__ __nv_bfloat16 g_wh[4][(size_t)D_*D_], g_wl[4][(size_t)D_*D_];  // transposed [n][k]
// attention operands, head-major [b][h][s][dk] bf16 splits (V same layout)
__device__ __nv_bfloat16 g_aqh[(size_t)M_*D_], g_aql[(size_t)M_*D_];
__device__ __nv_bfloat16 g_akh[(size_t)M_*D_], g_akl[(size_t)M_*D_];
__device__ __nv_bfloat16 g_avh[(size_t)M_*D_], g_avl[(size_t)M_*D_];

// ============================ PTX helpers (baseline ISA only) ================
__device__ __forceinline__ uint32_t smem_u32(const void* p) {
    uint32_t a;
    asm("{ .reg .u64 t; cvta.to.shared.u64 t, %1; cvt.u32.u64 %0, t; }" : "=r"(a) : "l"(p));
    return a;
}
__device__ __forceinline__ void cp_async16(uint32_t dst, const void* src) {
    asm volatile("cp.async.cg.shared.global [%0], [%1], 16;" :: "r"(dst), "l"(src));
}
__device__ __forceinline__ void cp_commit() {
    asm volatile("cp.async.commit_group;" ::: "memory");
}
template <int N>
__device__ __forceinline__ void cp_wait() {
    asm volatile("cp.async.wait_group %0;" :: "n"(N) : "memory");
}
__device__ __forceinline__ void ldsm4(uint32_t* r, uint32_t addr) {
    asm volatile("ldmatrix.sync.aligned.m8n8.x4.shared.b16 {%0,%1,%2,%3}, [%4];"
                 : "=r"(r[0]), "=r"(r[1]), "=r"(r[2]), "=r"(r[3]) : "r"(addr));
}
__device__ __forceinline__ void ldsm4t(uint32_t* r, uint32_t addr) {
    asm volatile("ldmatrix.sync.aligned.m8n8.x4.trans.shared.b16 {%0,%1,%2,%3}, [%4];"
                 : "=r"(r[0]), "=r"(r[1]), "=r"(r[2]), "=r"(r[3]) : "r"(addr));
}
__device__ __forceinline__ void mma16816(float* d, const uint32_t* a, const uint32_t* b) {
    asm volatile(
        "mma.sync.aligned.m16n8k16.row.col.f32.bf16.bf16.f32 "
        "{%0,%1,%2,%3}, {%4,%5,%6,%7}, {%8,%9}, {%0,%1,%2,%3};"
        : "+f"(d[0]), "+f"(d[1]), "+f"(d[2]), "+f"(d[3])
        : "r"(a[0]), "r"(a[1]), "r"(a[2]), "r"(a[3]), "r"(b[0]), "r"(b[1]));
}
__device__ __forceinline__ uint32_t sw128(uint32_t b) { return b ^ ((b >> 3) & 0x70); }
// pack two floats into bf16x2 reg: low element = first arg (validated R7)
__device__ __forceinline__ uint32_t pack_bf2(float lo, float hi) {
    uint32_t d;
    asm("cvt.rn.bf16x2.f32 %0, %1, %2;" : "=r"(d) : "f"(hi), "f"(lo));
    return d;
}
__device__ __forceinline__ float bf16rt(float v) {          // round-trip through bf16
    return __bfloat162float(__float2bfloat16_rn(v));
}

// ---------------- bias table -------------------------------------------------
__global__ void bias_kernel(const float* __restrict__ rel_emb) {
    int idx = blockIdx.x * blockDim.x + threadIdx.x;
    if (idx >= NDELTA) return;
    int delta = idx - (S_ - 1);      // k - q
    int n = -delta;
    int ret = (n < 0) ? (NBUCK / 2) : 0;
    n = (n < 0) ? -n : n;
    const int max_exact = NBUCK / 4; // 8
    int bv;
    if (n < max_exact) {
        bv = n;
    } else {
        int t;
        if ((n & (n - 1)) == 0) {           // power of two: exact boundary value
            int p = 31 - __clz(n);
            t = 2 * (p - 3);
        } else {
            t = (int)((logf((float)n / 8.0f) / logf(16.0f)) * 8.0f);
        }
        bv = max_exact + t;
        if (bv > NBUCK / 2 - 1) bv = NBUCK / 2 - 1;
    }
    int bucket = ret + bv;
    #pragma unroll
    for (int h = 0; h < H_; h++)
        g_bias[h * NDELTA + idx] = rel_emb[bucket * H_ + h];
}

// ---------------- bf16 split kernels -----------------------------------------
__global__ void split_act(const float4* __restrict__ src,
                          __nv_bfloat16* __restrict__ hi,
                          __nv_bfloat16* __restrict__ lo) {
    size_t i = (size_t)blockIdx.x * blockDim.x + threadIdx.x;
    float4 v = src[i];
    float vv[4] = {v.x, v.y, v.z, v.w};
    __nv_bfloat16 h[4], l[4];
    #pragma unroll
    for (int j = 0; j < 4; j++) {
        h[j] = __float2bfloat16(vv[j]);
        l[j] = __float2bfloat16(vv[j] - __bfloat162float(h[j]));
    }
    __nv_bfloat162* H = (__nv_bfloat162*)hi;
    __nv_bfloat162* L = (__nv_bfloat162*)lo;
    H[2*i]   = __nv_bfloat162(h[0], h[1]);
    H[2*i+1] = __nv_bfloat162(h[2], h[3]);
    L[2*i]   = __nv_bfloat162(l[0], l[1]);
    L[2*i+1] = __nv_bfloat162(l[2], l[3]);
}

// W [K][N] -> Wt [N][K] split into hi/lo
__global__ void split_wT(const float* __restrict__ W,
                         __nv_bfloat16* __restrict__ Th,
                         __nv_bfloat16* __restrict__ Tl) {
    __shared__ float t[32][33];
    const int n0 = blockIdx.x * 32, k0 = blockIdx.y * 32;
    for (int r = threadIdx.y; r < 32; r += 8)
        t[r][threadIdx.x] = W[(size_t)(k0 + r) * D_ + n0 + threadIdx.x];
    __syncthreads();
    for (int r = threadIdx.y; r < 32; r += 8) {
        float v = t[threadIdx.x][r];          // = W[k0+tx][n0+r]
        __nv_bfloat16 h = __float2bfloat16(v);
        size_t o = (size_t)(n0 + r) * D_ + k0 + threadIdx.x;
        Th[o] = h;
        Tl[o] = __float2bfloat16(v - __bfloat162float(h));
    }
}

// ============= fused QKV GEMM: 3 weight mats, head-major bf16-split out ======
#define GM 128
#define GN 128
#define GKC 64
#define NCHUNK (D_ / GKC)             // 16
#define TILE_B (128*128)              // bytes per bf16 tile
#define GSMEM  (2*4*TILE_B)           // 131072

__global__ void __launch_bounds__(256, 1)
qkv_gemm(const __nv_bfloat16* __restrict__ Ah, const __nv_bfloat16* __restrict__ Al,
         const __nv_bfloat16* __restrict__ Wh, const __nv_bfloat16* __restrict__ Wl,
         __nv_bfloat16* __restrict__ oqh, __nv_bfloat16* __restrict__ oql,
         __nv_bfloat16* __restrict__ okh, __nv_bfloat16* __restrict__ okl,
         __nv_bfloat16* __restrict__ ovh, __nv_bfloat16* __restrict__ ovl) {
    extern __shared__ char dsm[];
    const uint32_t smb = smem_u32(dsm);

    const int tid    = threadIdx.x;
    const int lane   = tid & 31;
    const int wid    = tid >> 5;
    const int warp_m = wid & 1;
    const int warp_n = wid >> 1;
    const int which  = blockIdx.x >> 3;                 // 0=Q 1=K 2=V
    const int n0     = (blockIdx.x & 7) * GN;
    const int m0     = blockIdx.y * GM;

    const __nv_bfloat16* Bh = Wh + (size_t)which * D_ * D_;
    const __nv_bfloat16* Bl = Wl + (size_t)which * D_ * D_;
    __nv_bfloat16* OH = (which == 0) ? oqh : (which == 1) ? okh : ovh;
    __nv_bfloat16* OL = (which == 0) ? oql : (which == 1) ? okl : ovl;

    float acc[4][4][4];
    #pragma unroll
    for (int i = 0; i < 4; i++)
        #pragma unroll
        for (int j = 0; j < 4; j++)
            #pragma unroll
            for (int k = 0; k < 4; k++) acc[i][j][k] = 0.f;

    auto prefetch = [&](int ch) {
        const int kc0 = ch * GKC;
        const uint32_t db = smb + (uint32_t)(ch & 1) * (4 * TILE_B);
        #pragma unroll
        for (int j = 0; j < 4; j++) {
            int ci  = tid + j * 256;
            int row = ci >> 3;
            int f4  = ci & 7;
            uint32_t so = sw128((uint32_t)(row * 128 + f4 * 16));
            size_t gaA = (size_t)(m0 + row) * D_ + kc0 + f4 * 8;
            size_t gaB = (size_t)(n0 + row) * D_ + kc0 + f4 * 8;
            cp_async16(db + 0*TILE_B + so, Ah + gaA);
            cp_async16(db + 1*TILE_B + so, Al + gaA);
            cp_async16(db + 2*TILE_B + so, Bh + gaB);
            cp_async16(db + 3*TILE_B + so, Bl + gaB);
        }
    };

    const int aRow = warp_m * 64 + (lane & 15);
    const int aKb  = (lane >> 4) * 16;
    const int bRow = warp_n * 32 + ((lane >> 4) << 3) + (lane & 7);
    const int bKb  = ((lane >> 3) & 1) * 16;

    prefetch(0);
    cp_commit();

    for (int ch = 0; ch < NCHUNK; ch++) {
        if (ch + 1 < NCHUNK) {
            prefetch(ch + 1);
            cp_commit();
            cp_wait<1>();
        } else {
            cp_wait<0>();
        }
        __syncthreads();

        const uint32_t base = smb + (uint32_t)(ch & 1) * (4 * TILE_B);
        const uint32_t aH = base, aL = base + TILE_B;
        const uint32_t bH = base + 2*TILE_B, bL = base + 3*TILE_B;

        #pragma unroll
        for (int ks = 0; ks < 4; ks++) {
            uint32_t a[4][4], bh[2][4], bl[2][4];
            #pragma unroll
            for (int mb = 0; mb < 4; mb++) {
                uint32_t off = sw128((uint32_t)((aRow + mb*16) * 128 + ks*32 + aKb));
                ldsm4(a[mb], aH + off);
            }
            #pragma unroll
            for (int nb2 = 0; nb2 < 2; nb2++) {
                uint32_t off = sw128((uint32_t)((bRow + nb2*16) * 128 + ks*32 + bKb));
                ldsm4(bh[nb2], bH + off);
                ldsm4(bl[nb2], bL + off);
            }
            #pragma unroll
            for (int mb = 0; mb < 4; mb++)
                #pragma unroll
                for (int nb = 0; nb < 4; nb++) {
                    mma16816(acc[mb][nb], a[mb], &bh[nb >> 1][(nb & 1) * 2]);
                    mma16816(acc[mb][nb], a[mb], &bl[nb >> 1][(nb & 1) * 2]);
                }
            #pragma unroll
            for (int mb = 0; mb < 4; mb++) {
                uint32_t off = sw128((uint32_t)((aRow + mb*16) * 128 + ks*32 + aKb));
                ldsm4(a[mb], aL + off);
            }
            #pragma unroll
            for (int mb = 0; mb < 4; mb++)
                #pragma unroll
                for (int nb = 0; nb < 4; nb++)
                    mma16816(acc[mb][nb], a[mb], &bh[nb >> 1][(nb & 1) * 2]);
        }
        __syncthreads();
    }

    // ---- epilogue: write head-major [b][h][s][dk] bf16 hi/lo ----
    const int rowE0 = m0 + warp_m * 64 + (lane >> 2);
    const int colE0 = n0 + warp_n * 32 + (lane & 3) * 2;
    #pragma unroll
    for (int mb = 0; mb < 4; mb++)
        #pragma unroll
        for (int nb = 0; nb < 4; nb++) {
            const int col = colE0 + nb * 8;
            const int h = col >> 6, dk = col & 63;
            #pragma unroll
            for (int half = 0; half < 2; half++) {
                const int mm = rowE0 + mb * 16 + half * 8;
                const int b = mm >> 10, s = mm & 1023;
                size_t dst = ((size_t)(b * H_ + h) * S_ + s) * DK_ + dk;
                float v0 = acc[mb][nb][half*2], v1 = acc[mb][nb][half*2 + 1];
                float h0 = bf16rt(v0), h1 = bf16rt(v1);
                *(uint32_t*)(OH + dst) = pack_bf2(v0, v1);
                *(uint32_t*)(OL + dst) = pack_bf2(v0 - h0, v1 - h1);
            }
        }
}

// ---------------- HMMA bf16x3 GEMM (Wo): fp32 out ---------------------------
__global__ void __launch_bounds__(256, 1)
gemm_bf16x3(const __nv_bfloat16* __restrict__ Ah, const __nv_bfloat16* __restrict__ Al,
            const __nv_bfloat16* __restrict__ Bh, const __nv_bfloat16* __restrict__ Bl,
            float* __restrict__ C) {
    extern __shared__ char dsm[];
    const uint32_t smb = smem_u32(dsm);

    const int tid    = threadIdx.x;
    const int lane   = tid & 31;
    const int wid    = tid >> 5;
    const int warp_m = wid & 1;
    const int warp_n = wid >> 1;
    const int m0 = blockIdx.y * GM, n0 = blockIdx.x * GN;

    float acc[4][4][4];
    #pragma unroll
    for (int i = 0; i < 4; i++)
        #pragma unroll
        for (int j = 0; j < 4; j++)
            #pragma unroll
            for (int k = 0; k < 4; k++) acc[i][j][k] = 0.f;

    auto prefetch = [&](int ch) {
        const int kc0 = ch * GKC;
        const uint32_t db = smb + (uint32_t)(ch & 1) * (4 * TILE_B);
        #pragma unroll
        for (int j = 0; j < 4; j++) {
            int ci  = tid + j * 256;
            int row = ci >> 3;
            int f4  = ci & 7;
            uint32_t so = sw128((uint32_t)(row * 128 + f4 * 16));
            size_t gaA = (size_t)(m0 + row) * D_ + kc0 + f4 * 8;
            size_t gaB = (size_t)(n0 + row) * D_ + kc0 + f4 * 8;
            cp_async16(db + 0*TILE_B + so, Ah + gaA);
            cp_async16(db + 1*TILE_B + so, Al + gaA);
            cp_async16(db + 2*TILE_B + so, Bh + gaB);
            cp_async16(db + 3*TILE_B + so, Bl + gaB);
        }
    };

    const int aRow = warp_m * 64 + (lane & 15);
    const int aKb  = (lane >> 4) * 16;
    const int bRow = warp_n * 32 + ((lane >> 4) << 3) + (lane & 7);
    const int bKb  = ((lane >> 3) & 1) * 16;

    prefetch(0);
    cp_commit();

    for (int ch = 0; ch < NCHUNK; ch++) {
        if (ch + 1 < NCHUNK) {
            prefetch(ch + 1);
            cp_commit();
            cp_wait<1>();
        } else {
            cp_wait<0>();
        }
        __syncthreads();

        const uint32_t base = smb + (uint32_t)(ch & 1) * (4 * TILE_B);
        const uint32_t aH = base, aL = base + TILE_B;
        const uint32_t bH = base + 2*TILE_B, bL = base + 3*TILE_B;

        #pragma unroll
        for (int ks = 0; ks < 4; ks++) {
            uint32_t a[4][4], bh[2][4], bl[2][4];
            #pragma unroll
            for (int mb = 0; mb < 4; mb++) {
                uint32_t off = sw128((uint32_t)((aRow + mb*16) * 128 + ks*32 + aKb));
                ldsm4(a[mb], aH + off);
            }
            #pragma unroll
            for (int nb2 = 0; nb2 < 2; nb2++) {
                uint32_t off = sw128((uint32_t)((bRow + nb2*16) * 128 + ks*32 + bKb));
                ldsm4(bh[nb2], bH + off);
                ldsm4(bl[nb2], bL + off);
            }
            #pragma unroll
            for (int mb = 0; mb < 4; mb++)
                #pragma unroll
                for (int nb = 0; nb < 4; nb++) {
                    mma16816(acc[mb][nb], a[mb], &bh[nb >> 1][(nb & 1) * 2]);
                    mma16816(acc[mb][nb], a[mb], &bl[nb >> 1][(nb & 1) * 2]);
                }
            #pragma unroll
            for (int mb = 0; mb < 4; mb++) {
                uint32_t off = sw128((uint32_t)((aRow + mb*16) * 128 + ks*32 + aKb));
                ldsm4(a[mb], aL + off);
            }
            #pragma unroll
            for (int mb = 0; mb < 4; mb++)
                #pragma unroll
                for (int nb = 0; nb < 4; nb++)
                    mma16816(acc[mb][nb], a[mb], &bh[nb >> 1][(nb & 1) * 2]);
        }
        __syncthreads();
    }

    const int rowE = m0 + warp_m * 64 + (lane >> 2);
    const int colE = n0 + warp_n * 32 + (lane & 3) * 2;
    #pragma unroll
    for (int mb = 0; mb < 4; mb++)
        #pragma unroll
        for (int nb = 0; nb < 4; nb++) {
            float* p = C + (size_t)(rowE + mb*16) * D_ + colE + nb*8;
            *(float2*)p            = make_float2(acc[mb][nb][0], acc[mb][nb][1]);
            *(float2*)(p + 8*D_)   = make_float2(acc[mb][nb][2], acc[mb][nb][3]);
        }
}

// ---------------- HMMA flash attention (V via trans-ldmatrix) ----------------
#define AQ 128
#define AK 64
#define A_KVT    8192                 // 64 rows x 128B
#define A_BUFSZ (4*A_KVT)             // Kh,Kl,Vh,Vl
#define A_SMQH  0
#define A_SMQL  16384
#define A_SMBUF 32768
#define A_SMBIAS (32768 + 2*A_BUFSZ)  // 98304
#define A_SMEM  (A_SMBIAS + 2*192*4)  // 99840

__global__ void __launch_bounds__(256, 1)
attn_mma(const __nv_bfloat16* __restrict__ Qh, const __nv_bfloat16* __restrict__ Ql,
         const __nv_bfloat16* __restrict__ Kh, const __nv_bfloat16* __restrict__ Kl,
         const __nv_bfloat16* __restrict__ Vh, const __nv_bfloat16* __restrict__ Vl,
         __nv_bfloat16* __restrict__ ctxh, __nv_bfloat16* __restrict__ ctxl) {
    extern __shared__ char dsm[];
    const uint32_t smb = smem_u32(dsm);
    float* bias_s = (float*)(dsm + A_SMBIAS);   // [2][192]

    const int tid  = threadIdx.x;
    const int lane = tid & 31;
    const int w    = tid >> 5;
    const int q0 = blockIdx.x * AQ;
    const int h  = blockIdx.y;
    const int b  = blockIdx.z;
    const int bh = b * H_ + h;

    const int aRow = w * 16 + (lane & 15);
    const int aKb  = (lane >> 4) * 16;
    const int bRowB = ((lane >> 4) << 3) + (lane & 7);
    const int bKb   = ((lane >> 3) & 1) * 16;
    // trans-ldmatrix (V) address components: mat = lane>>3
    const int vRow = (((lane >> 3) & 1) << 3) + (lane & 7);   // s within 16-chunk
    const int vKb  = (lane >> 4) * 16;                        // d-byte within 32B chunk

    // ---- load Q tiles ----
    #pragma unroll
    for (int j = 0; j < 4; j++) {
        int ci = tid + j * 256;
        int row = ci >> 3, f4 = ci & 7;
        uint32_t so = sw128((uint32_t)(row * 128 + f4 * 16));
        size_t ga = ((size_t)bh * S_ + q0 + row) * DK_ + f4 * 8;
        cp_async16(smb + A_SMQH + so, Qh + ga);
        cp_async16(smb + A_SMQL + so, Ql + ga);
    }

    auto prefetch = [&](int it) {
        const int k0 = it * AK;
        const uint32_t db = smb + A_SMBUF + (uint32_t)(it & 1) * A_BUFSZ;
        #pragma unroll
        for (int j = 0; j < 2; j++) {
            int ci = tid + j * 256;
            int row = ci >> 3, f4 = ci & 7;
            uint32_t so = sw128((uint32_t)(row * 128 + f4 * 16));
            size_t g = ((size_t)bh * S_ + k0 + row) * DK_ + f4 * 8;
            cp_async16(db + 0*A_KVT + so, Kh + g);
            cp_async16(db + 1*A_KVT + so, Kl + g);
            cp_async16(db + 2*A_KVT + so, Vh + g);
            cp_async16(db + 3*A_KVT + so, Vl + g);
        }
    };
    auto stage_bias = [&](int it) {
        if (tid < 191)
            bias_s[(it & 1) * 192 + tid] =
                g_bias[h * NDELTA + it * AK - q0 + tid + 896];
    };

    prefetch(0);
    stage_bias(0);
    cp_commit();

    float m0r = -INFINITY, m1r = -INFINITY, l0 = 0.f, l1 = 0.f;
    float oa[8][4];
    #pragma unroll
    for (int i = 0; i < 8; i++)
        #pragma unroll
        for (int j = 0; j < 4; j++) oa[i][j] = 0.f;

    const int kcb = (lane & 3) * 2;
    const int rql = w * 16 + (lane >> 2);

    for (int it = 0; it < S_ / AK; it++) {
        if (it + 1 < S_ / AK) {
            prefetch(it + 1);
            stage_bias(it + 1);
            cp_commit();
            cp_wait<1>();
        } else {
            cp_wait<0>();
        }
        __syncthreads();

        const uint32_t base = smb + A_SMBUF + (uint32_t)(it & 1) * A_BUFSZ;
        const uint32_t kH = base, kL = base + A_KVT;
        const uint32_t vH = base + 2*A_KVT, vL = base + 3*A_KVT;
        const float* bp = bias_s + (it & 1) * 192;

        // ---- scores ----
        float sa[8][4];
        #pragma unroll
        for (int i = 0; i < 8; i++)
            #pragma unroll
            for (int j = 0; j < 4; j++) sa[i][j] = 0.f;

        #pragma unroll
        for (int ks = 0; ks < 4; ks++) {
            uint32_t qh_f[4], ql_f[4];
            uint32_t qoff = sw128((uint32_t)(aRow * 128 + ks*32 + aKb));
            ldsm4(qh_f, smb + A_SMQH + qoff);
            ldsm4(ql_f, smb + A_SMQL + qoff);
            uint32_t khf[4][4], klf[4][4];
            #pragma unroll
            for (int nb2 = 0; nb2 < 4; nb2++) {
                uint32_t off = sw128((uint32_t)((bRowB + nb2*16) * 128 + ks*32 + bKb));
                ldsm4(khf[nb2], kH + off);
                ldsm4(klf[nb2], kL + off);
            }
            #pragma unroll
            for (int t = 0; t < 8; t++) {
                uint32_t* bhp = &khf[t >> 1][(t & 1) * 2];
                uint32_t* blp = &klf[t >> 1][(t & 1) * 2];
                mma16816(sa[t], qh_f, bhp);
                mma16816(sa[t], qh_f, blp);
                mma16816(sa[t], ql_f, bhp);
            }
        }

        // ---- bias + online softmax ----
        float mx0 = -INFINITY, mx1 = -INFINITY;
        #pragma unroll
        for (int t = 0; t < 8; t++) {
            int bi = t*8 + kcb - rql + 127;
            float s0 = sa[t][0] + bp[bi];
            float s1 = sa[t][1] + bp[bi + 1];
            float s2 = sa[t][2] + bp[bi - 8];
            float s3 = sa[t][3] + bp[bi - 7];
            sa[t][0] = s0; sa[t][1] = s1; sa[t][2] = s2; sa[t][3] = s3;
            mx0 = fmaxf(mx0, fmaxf(s0, s1));
            mx1 = fmaxf(mx1, fmaxf(s2, s3));
        }
        mx0 = fmaxf(mx0, __shfl_xor_sync(0xffffffffu, mx0, 1));
        mx0 = fmaxf(mx0, __shfl_xor_sync(0xffffffffu, mx0, 2));
        mx1 = fmaxf(mx1, __shfl_xor_sync(0xffffffffu, mx1, 1));
        mx1 = fmaxf(mx1, __shfl_xor_sync(0xffffffffu, mx1, 2));
        float mn0 = fmaxf(m0r, mx0), mn1 = fmaxf(m1r, mx1);
        float c0 = __expf(m0r - mn0), c1 = __expf(m1r - mn1);
        l0 *= c0; l1 *= c1;
        #pragma unroll
        for (int dt = 0; dt < 8; dt++) {
            oa[dt][0] *= c0; oa[dt][1] *= c0;
            oa[dt][2] *= c1; oa[dt][3] *= c1;
        }
        m0r = mn0; m1r = mn1;
        #pragma unroll
        for (int t = 0; t < 8; t++) {
            float p0 = __expf(sa[t][0] - mn0);
            float p1 = __expf(sa[t][1] - mn0);
            float p2 = __expf(sa[t][2] - mn1);
            float p3 = __expf(sa[t][3] - mn1);
            l0 += p0 + p1; l1 += p2 + p3;
            sa[t][0] = p0; sa[t][1] = p1; sa[t][2] = p2; sa[t][3] = p3;
        }

        // ---- PV: V loaded transposed from [s][dk] layout ----
        #pragma unroll
        for (int ks = 0; ks < 4; ks++) {
            const int t0 = 2*ks, t1 = 2*ks + 1;
            uint32_t pah[4], pal[4];
            #pragma unroll
            for (int half = 0; half < 2; half++) {
                const int tt = half ? t1 : t0;
                float p0 = sa[tt][0], p1 = sa[tt][1], p2 = sa[tt][2], p3 = sa[tt][3];
                float h0 = bf16rt(p0), h1 = bf16rt(p1), h2 = bf16rt(p2), h3 = bf16rt(p3);
                pah[half*2 + 0] = pack_bf2(p0, p1);
                pah[half*2 + 1] = pack_bf2(p2, p3);
                pal[half*2 + 0] = pack_bf2(p0 - h0, p1 - h1);
                pal[half*2 + 1] = pack_bf2(p2 - h2, p3 - h3);
            }
            uint32_t vhf[4][4], vlf[4][4];
            #pragma unroll
            for (int nb2 = 0; nb2 < 4; nb2++) {
                uint32_t off = sw128((uint32_t)((ks*16 + vRow) * 128 + nb2*32 + vKb));
                ldsm4t(vhf[nb2], vH + off);
                ldsm4t(vlf[nb2], vL + off);
            }
            #pragma unroll
            for (int dt = 0; dt < 8; dt++) {
                uint32_t* b1 = &vhf[dt >> 1][(dt & 1) * 2];
                uint32_t* b2 = &vlf[dt >> 1][(dt & 1) * 2];
                mma16816(oa[dt], pah, b1);
                mma16816(oa[dt], pah, b2);
                mma16816(oa[dt], pal, b1);
            }
        }
        __syncthreads();
    }

    // ---- finalize: write ctx as bf16 hi/lo split [m][h*dk] ----
    l0 += __shfl_xor_sync(0xffffffffu, l0, 1);
    l0 += __shfl_xor_sync(0xffffffffu, l0, 2);
    l1 += __shfl_xor_sync(0xffffffffu, l1, 1);
    l1 += __shfl_xor_sync(0xffffffffu, l1, 2);
    float inv0 = 1.f / l0, inv1 = 1.f / l1;
    const int rowg = b * S_ + q0 + rql;
    #pragma unroll
    for (int dt = 0; dt < 8; dt++) {
        size_t dst = (size_t)rowg * D_ + h * DK_ + dt*8 + kcb;
        float v0 = oa[dt][0] * inv0, v1 = oa[dt][1] * inv0;
        float v2 = oa[dt][2] * inv1, v3 = oa[dt][3] * inv1;
        float h0 = bf16rt(v0), h1 = bf16rt(v1), h2 = bf16rt(v2), h3 = bf16rt(v3);
        *(uint32_t*)(ctxh + dst)          = pack_bf2(v0, v1);
        *(uint32_t*)(ctxl + dst)          = pack_bf2(v0 - h0, v1 - h1);
        *(uint32_t*)(ctxh + dst + 8*D_)   = pack_bf2(v2, v3);
        *(uint32_t*)(ctxl + dst + 8*D_)   = pack_bf2(v2 - h2, v3 - h3);
    }
}

// ---------------- launch -----------------------------------------------------
extern "C" void kernel_launch(void* const* d_in, const int* in_sizes, int n_in,
                              void* d_out, int out_size) {
    const float* x   = (const float*)d_in[0];
    const float* Wq  = (const float*)d_in[1];
    const float* Wk  = (const float*)d_in[2];
    const float* Wv  = (const float*)d_in[3];
    const float* Wo  = (const float*)d_in[4];
    const float* rel = (const float*)d_in[5];
    float* out = (float*)d_out;

    __nv_bfloat16 *xh, *xl, *chh, *cll, *wh, *wl;
    cudaGetSymbolAddress((void**)&xh, g_xh);
    cudaGetSymbolAddress((void**)&xl, g_xl);
    cudaGetSymbolAddress((void**)&chh, g_ch);
    cudaGetSymbolAddress((void**)&cll, g_cl);
    cudaGetSymbolAddress((void**)&wh, g_wh);
    cudaGetSymbolAddress((void**)&wl, g_wl);
    __nv_bfloat16 *aqh, *aql, *akh, *akl, *avh, *avl;
    cudaGetSymbolAddress((void**)&aqh, g_aqh);
    cudaGetSymbolAddress((void**)&aql, g_aql);
    cudaGetSymbolAddress((void**)&akh, g_akh);
    cudaGetSymbolAddress((void**)&akl, g_akl);
    cudaGetSymbolAddress((void**)&avh, g_avh);
    cudaGetSymbolAddress((void**)&avl, g_avl);

    cudaFuncSetAttribute(qkv_gemm,    cudaFuncAttributeMaxDynamicSharedMemorySize, GSMEM);
    cudaFuncSetAttribute(gemm_bf16x3, cudaFuncAttributeMaxDynamicSharedMemorySize, GSMEM);
    cudaFuncSetAttribute(attn_mma,    cudaFuncAttributeMaxDynamicSharedMemorySize, A_SMEM);

    bias_kernel<<<(NDELTA + 127) / 128, 128>>>(rel);

    split_act<<<(M_ * D_ / 4) / 256, 256>>>((const float4*)x, xh, xl);
    {
        dim3 gt(32, 32), bt(32, 8);
        const float* Ws[4] = {Wq, Wk, Wv, Wo};
        for (int i = 0; i < 4; i++)
            split_wT<<<gt, bt>>>(Ws[i], wh + (size_t)i * D_ * D_, wl + (size_t)i * D_ * D_);
    }

    dim3 gq(24, 64);             // 3 weight mats x 8 n-tiles, 64 m-tiles
    qkv_gemm<<<gq, 256, GSMEM>>>(xh, xl, wh, wl, aqh, aql, akh, akl, avh, avl);

    dim3 ga(S_ / AQ, H_, B_);    // (8, 16, 8)
    attn_mma<<<ga, 256, A_SMEM>>>(aqh, aql, akh, akl, avh, avl, chh, cll);

    dim3 gg(D_ / GN, M_ / GM);   // (8, 64)
    gemm_bf16x3<<<gg, 256, GSMEM>>>(chh, cll, wh + 3*(size_t)D_*D_, wl + 3*(size_t)D_*D_, out);
}

// round 9
// speedup vs baseline: 5.1610x; 1.0026x over previous
#include <cuda_runtime.h>
#include <cuda_bf16.h>
#include <math.h>
#include <stdint.h>

#define B_   8
#define S_   1024
#define D_   1024
#define H_   16
#define DK_  64
#define M_   (B_*S_)          // 8192 rows
#define NBUCK 32
#define NDELTA (2*S_-1)       // 2047

// ---------------- scratch (device globals: no cudaMalloc allowed) ------------
__device__ float g_bias[H_*NDELTA];   // [h][delta+1023]
__device__ __nv_bfloat16 g_xh[(size_t)M_*D_], g_xl[(size_t)M_*D_];
__device__ __nv_bfloat16 g_ch[(size_t)M_*D_], g_cl[(size_t)M_*D_];   // ctx split
__device__ __nv_bfloat16 g_wh[4][(size_t)D_*D_], g_wl[4][(size_t)D_*D_];  // [n][k]
__device__ __nv_bfloat16 g_aqh[(size_t)M_*D_], g_aql[(size_t)M_*D_];  // [b][h][s][dk]
__device__ __nv_bfloat16 g_akh[(size_t)M_*D_], g_akl[(size_t)M_*D_];
__device__ __nv_bfloat16 g_avh[(size_t)M_*D_], g_avl[(size_t)M_*D_];

// ============================ PTX helpers (baseline ISA only) ================
__device__ __forceinline__ uint32_t smem_u32(const void* p) {
    uint32_t a;
    asm("{ .reg .u64 t; cvta.to.shared.u64 t, %1; cvt.u32.u64 %0, t; }" : "=r"(a) : "l"(p));
    return a;
}
__device__ __forceinline__ void cp_async16(uint32_t dst, const void* src) {
    asm volatile("cp.async.cg.shared.global [%0], [%1], 16;" :: "r"(dst), "l"(src));
}
__device__ __forceinline__ void cp_commit() {
    asm volatile("cp.async.commit_group;" ::: "memory");
}
template <int N>
__device__ __forceinline__ void cp_wait() {
    asm volatile("cp.async.wait_group %0;" :: "n"(N) : "memory");
}
__device__ __forceinline__ void ldsm4(uint32_t* r, uint32_t addr) {
    asm volatile("ldmatrix.sync.aligned.m8n8.x4.shared.b16 {%0,%1,%2,%3}, [%4];"
                 : "=r"(r[0]), "=r"(r[1]), "=r"(r[2]), "=r"(r[3]) : "r"(addr));
}
__device__ __forceinline__ void ldsm4t(uint32_t* r, uint32_t addr) {
    asm volatile("ldmatrix.sync.aligned.m8n8.x4.trans.shared.b16 {%0,%1,%2,%3}, [%4];"
                 : "=r"(r[0]), "=r"(r[1]), "=r"(r[2]), "=r"(r[3]) : "r"(addr));
}
__device__ __forceinline__ void mma16816(float* d, const uint32_t* a, const uint32_t* b) {
    asm volatile(
        "mma.sync.aligned.m16n8k16.row.col.f32.bf16.bf16.f32 "
        "{%0,%1,%2,%3}, {%4,%5,%6,%7}, {%8,%9}, {%0,%1,%2,%3};"
        : "+f"(d[0]), "+f"(d[1]), "+f"(d[2]), "+f"(d[3])
        : "r"(a[0]), "r"(a[1]), "r"(a[2]), "r"(a[3]), "r"(b[0]), "r"(b[1]));
}
__device__ __forceinline__ uint32_t sw128(uint32_t b) { return b ^ ((b >> 3) & 0x70); }
__device__ __forceinline__ uint32_t pack_bf2(float lo, float hi) {
    uint32_t d;
    asm("cvt.rn.bf16x2.f32 %0, %1, %2;" : "=r"(d) : "f"(hi), "f"(lo));
    return d;
}
__device__ __forceinline__ float bf16rt(float v) {
    return __bfloat162float(__float2bfloat16_rn(v));
}

// ---------------- bias table -------------------------------------------------
__global__ void bias_kernel(const float* __restrict__ rel_emb) {
    int idx = blockIdx.x * blockDim.x + threadIdx.x;
    if (idx >= NDELTA) return;
    int delta = idx - (S_ - 1);      // k - q
    int n = -delta;
    int ret = (n < 0) ? (NBUCK / 2) : 0;
    n = (n < 0) ? -n : n;
    const int max_exact = NBUCK / 4; // 8
    int bv;
    if (n < max_exact) {
        bv = n;
    } else {
        int t;
        if ((n & (n - 1)) == 0) {           // power of two: exact boundary value
            int p = 31 - __clz(n);
            t = 2 * (p - 3);
        } else {
            t = (int)((logf((float)n / 8.0f) / logf(16.0f)) * 8.0f);
        }
        bv = max_exact + t;
        if (bv > NBUCK / 2 - 1) bv = NBUCK / 2 - 1;
    }
    int bucket = ret + bv;
    #pragma unroll
    for (int h = 0; h < H_; h++)
        g_bias[h * NDELTA + idx] = rel_emb[bucket * H_ + h];
}

// ---------------- bf16 split kernels -----------------------------------------
__global__ void split_act(const float4* __restrict__ src,
                          __nv_bfloat16* __restrict__ hi,
                          __nv_bfloat16* __restrict__ lo) {
    size_t i = (size_t)blockIdx.x * blockDim.x + threadIdx.x;
    float4 v = src[i];
    float vv[4] = {v.x, v.y, v.z, v.w};
    __nv_bfloat16 h[4], l[4];
    #pragma unroll
    for (int j = 0; j < 4; j++) {
        h[j] = __float2bfloat16(vv[j]);
        l[j] = __float2bfloat16(vv[j] - __bfloat162float(h[j]));
    }
    __nv_bfloat162* H = (__nv_bfloat162*)hi;
    __nv_bfloat162* L = (__nv_bfloat162*)lo;
    H[2*i]   = __nv_bfloat162(h[0], h[1]);
    H[2*i+1] = __nv_bfloat162(h[2], h[3]);
    L[2*i]   = __nv_bfloat162(l[0], l[1]);
    L[2*i+1] = __nv_bfloat162(l[2], l[3]);
}

// all 4 weights in one launch: W [K][N] -> Wt [N][K] split hi/lo
__global__ void split_wT(const float* __restrict__ W0, const float* __restrict__ W1,
                         const float* __restrict__ W2, const float* __restrict__ W3,
                         __nv_bfloat16* __restrict__ Th,
                         __nv_bfloat16* __restrict__ Tl) {
    __shared__ float t[32][33];
    const int which = blockIdx.z;
    const float* W = (which == 0) ? W0 : (which == 1) ? W1 : (which == 2) ? W2 : W3;
    __nv_bfloat16* TH = Th + (size_t)which * D_ * D_;
    __nv_bfloat16* TL = Tl + (size_t)which * D_ * D_;
    const int n0 = blockIdx.x * 32, k0 = blockIdx.y * 32;
    for (int r = threadIdx.y; r < 32; r += 8)
        t[r][threadIdx.x] = W[(size_t)(k0 + r) * D_ + n0 + threadIdx.x];
    __syncthreads();
    for (int r = threadIdx.y; r < 32; r += 8) {
        float v = t[threadIdx.x][r];
        __nv_bfloat16 h = __float2bfloat16(v);
        size_t o = (size_t)(n0 + r) * D_ + k0 + threadIdx.x;
        TH[o] = h;
        TL[o] = __float2bfloat16(v - __bfloat162float(h));
    }
}

// ============= fused QKV GEMM: 3-stage pipeline, head-major split out ========
#define GM 128
#define GN 128
#define GKC 64
#define NCHUNK (D_ / GKC)             // 16
#define TILE_B (128*128)              // 16384 bytes per tile
#define STAGE_B (4*TILE_B)            // 65536
#define GSMEM  (3*STAGE_B)            // 196608

__global__ void __launch_bounds__(256, 1)
qkv_gemm(const __nv_bfloat16* __restrict__ Ah, const __nv_bfloat16* __restrict__ Al,
         const __nv_bfloat16* __restrict__ Wh, const __nv_bfloat16* __restrict__ Wl,
         __nv_bfloat16* __restrict__ oqh, __nv_bfloat16* __restrict__ oql,
         __nv_bfloat16* __restrict__ okh, __nv_bfloat16* __restrict__ okl,
         __nv_bfloat16* __restrict__ ovh, __nv_bfloat16* __restrict__ ovl) {
    extern __shared__ char dsm[];
    const uint32_t smb = smem_u32(dsm);

    const int tid    = threadIdx.x;
    const int lane   = tid & 31;
    const int wid    = tid >> 5;
    const int warp_m = wid & 1;
    const int warp_n = wid >> 1;
    const int which  = blockIdx.x >> 3;                 // 0=Q 1=K 2=V
    const int n0     = (blockIdx.x & 7) * GN;
    const int m0     = blockIdx.y * GM;

    const __nv_bfloat16* Bh = Wh + (size_t)which * D_ * D_;
    const __nv_bfloat16* Bl = Wl + (size_t)which * D_ * D_;
    __nv_bfloat16* OH = (which == 0) ? oqh : (which == 1) ? okh : ovh;
    __nv_bfloat16* OL = (which == 0) ? oql : (which == 1) ? okl : ovl;

    float acc[4][4][4];
    #pragma unroll
    for (int i = 0; i < 4; i++)
        #pragma unroll
        for (int j = 0; j < 4; j++)
            #pragma unroll
            for (int k = 0; k < 4; k++) acc[i][j][k] = 0.f;

    auto prefetch = [&](int ch) {
        const int kc0 = ch * GKC;
        const uint32_t db = smb + (uint32_t)(ch % 3) * STAGE_B;
        #pragma unroll
        for (int j = 0; j < 4; j++) {
            int ci  = tid + j * 256;
            int row = ci >> 3;
            int f4  = ci & 7;
            uint32_t so = sw128((uint32_t)(row * 128 + f4 * 16));
            size_t gaA = (size_t)(m0 + row) * D_ + kc0 + f4 * 8;
            size_t gaB = (size_t)(n0 + row) * D_ + kc0 + f4 * 8;
            cp_async16(db + 0*TILE_B + so, Ah + gaA);
            cp_async16(db + 1*TILE_B + so, Al + gaA);
            cp_async16(db + 2*TILE_B + so, Bh + gaB);
            cp_async16(db + 3*TILE_B + so, Bl + gaB);
        }
    };

    const int aRow = warp_m * 64 + (lane & 15);
    const int aKb  = (lane >> 4) * 16;
    const int bRow = warp_n * 32 + ((lane >> 4) << 3) + (lane & 7);
    const int bKb  = ((lane >> 3) & 1) * 16;

    prefetch(0); cp_commit();
    prefetch(1); cp_commit();

    for (int ch = 0; ch < NCHUNK; ch++) {
        if (ch + 1 < NCHUNK) cp_wait<1>(); else cp_wait<0>();
        __syncthreads();                        // single barrier per chunk
        if (ch + 2 < NCHUNK) { prefetch(ch + 2); cp_commit(); }

        const uint32_t base = smb + (uint32_t)(ch % 3) * STAGE_B;
        const uint32_t aH = base, aL = base + TILE_B;
        const uint32_t bH = base + 2*TILE_B, bL = base + 3*TILE_B;

        #pragma unroll
        for (int ks = 0; ks < 4; ks++) {
            uint32_t a[4][4], bh[2][4], bl[2][4];
            #pragma unroll
            for (int mb = 0; mb < 4; mb++) {
                uint32_t off = sw128((uint32_t)((aRow + mb*16) * 128 + ks*32 + aKb));
                ldsm4(a[mb], aH + off);
            }
            #pragma unroll
            for (int nb2 = 0; nb2 < 2; nb2++) {
                uint32_t off = sw128((uint32_t)((bRow + nb2*16) * 128 + ks*32 + bKb));
                ldsm4(bh[nb2], bH + off);
                ldsm4(bl[nb2], bL + off);
            }
            #pragma unroll
            for (int mb = 0; mb < 4; mb++)
                #pragma unroll
                for (int nb = 0; nb < 4; nb++) {
                    mma16816(acc[mb][nb], a[mb], &bh[nb >> 1][(nb & 1) * 2]);
                    mma16816(acc[mb][nb], a[mb], &bl[nb >> 1][(nb & 1) * 2]);
                }
            #pragma unroll
            for (int mb = 0; mb < 4; mb++) {
                uint32_t off = sw128((uint32_t)((aRow + mb*16) * 128 + ks*32 + aKb));
                ldsm4(a[mb], aL + off);
            }
            #pragma unroll
            for (int mb = 0; mb < 4; mb++)
                #pragma unroll
                for (int nb = 0; nb < 4; nb++)
                    mma16816(acc[mb][nb], a[mb], &bh[nb >> 1][(nb & 1) * 2]);
        }
    }

    // ---- epilogue: head-major [b][h][s][dk] bf16 hi/lo ----
    const int rowE0 = m0 + warp_m * 64 + (lane >> 2);
    const int colE0 = n0 + warp_n * 32 + (lane & 3) * 2;
    #pragma unroll
    for (int mb = 0; mb < 4; mb++)
        #pragma unroll
        for (int nb = 0; nb < 4; nb++) {
            const int col = colE0 + nb * 8;
            const int h = col >> 6, dk = col & 63;
            #pragma unroll
            for (int half = 0; half < 2; half++) {
                const int mm = rowE0 + mb * 16 + half * 8;
                const int b = mm >> 10, s = mm & 1023;
                size_t dst = ((size_t)(b * H_ + h) * S_ + s) * DK_ + dk;
                float v0 = acc[mb][nb][half*2], v1 = acc[mb][nb][half*2 + 1];
                float h0 = bf16rt(v0), h1 = bf16rt(v1);
                *(uint32_t*)(OH + dst) = pack_bf2(v0, v1);
                *(uint32_t*)(OL + dst) = pack_bf2(v0 - h0, v1 - h1);
            }
        }
}

// ---------------- HMMA bf16x3 GEMM (Wo): 3-stage, fp32 out -------------------
__global__ void __launch_bounds__(256, 1)
gemm_bf16x3(const __nv_bfloat16* __restrict__ Ah, const __nv_bfloat16* __restrict__ Al,
            const __nv_bfloat16* __restrict__ Bh, const __nv_bfloat16* __restrict__ Bl,
            float* __restrict__ C) {
    extern __shared__ char dsm[];
    const uint32_t smb = smem_u32(dsm);

    const int tid    = threadIdx.x;
    const int lane   = tid & 31;
    const int wid    = tid >> 5;
    const int warp_m = wid & 1;
    const int warp_n = wid >> 1;
    const int m0 = blockIdx.y * GM, n0 = blockIdx.x * GN;

    float acc[4][4][4];
    #pragma unroll
    for (int i = 0; i < 4; i++)
        #pragma unroll
        for (int j = 0; j < 4; j++)
            #pragma unroll
            for (int k = 0; k < 4; k++) acc[i][j][k] = 0.f;

    auto prefetch = [&](int ch) {
        const int kc0 = ch * GKC;
        const uint32_t db = smb + (uint32_t)(ch % 3) * STAGE_B;
        #pragma unroll
        for (int j = 0; j < 4; j++) {
            int ci  = tid + j * 256;
            int row = ci >> 3;
            int f4  = ci & 7;
            uint32_t so = sw128((uint32_t)(row * 128 + f4 * 16));
            size_t gaA = (size_t)(m0 + row) * D_ + kc0 + f4 * 8;
            size_t gaB = (size_t)(n0 + row) * D_ + kc0 + f4 * 8;
            cp_async16(db + 0*TILE_B + so, Ah + gaA);
            cp_async16(db + 1*TILE_B + so, Al + gaA);
            cp_async16(db + 2*TILE_B + so, Bh + gaB);
            cp_async16(db + 3*TILE_B + so, Bl + gaB);
        }
    };

    const int aRow = warp_m * 64 + (lane & 15);
    const int aKb  = (lane >> 4) * 16;
    const int bRow = warp_n * 32 + ((lane >> 4) << 3) + (lane & 7);
    const int bKb  = ((lane >> 3) & 1) * 16;

    prefetch(0); cp_commit();
    prefetch(1); cp_commit();

    for (int ch = 0; ch < NCHUNK; ch++) {
        if (ch + 1 < NCHUNK) cp_wait<1>(); else cp_wait<0>();
        __syncthreads();
        if (ch + 2 < NCHUNK) { prefetch(ch + 2); cp_commit(); }

        const uint32_t base = smb + (uint32_t)(ch % 3) * STAGE_B;
        const uint32_t aH = base, aL = base + TILE_B;
        const uint32_t bH = base + 2*TILE_B, bL = base + 3*TILE_B;

        #pragma unroll
        for (int ks = 0; ks < 4; ks++) {
            uint32_t a[4][4], bh[2][4], bl[2][4];
            #pragma unroll
            for (int mb = 0; mb < 4; mb++) {
                uint32_t off = sw128((uint32_t)((aRow + mb*16) * 128 + ks*32 + aKb));
                ldsm4(a[mb], aH + off);
            }
            #pragma unroll
            for (int nb2 = 0; nb2 < 2; nb2++) {
                uint32_t off = sw128((uint32_t)((bRow + nb2*16) * 128 + ks*32 + bKb));
                ldsm4(bh[nb2], bH + off);
                ldsm4(bl[nb2], bL + off);
            }
            #pragma unroll
            for (int mb = 0; mb < 4; mb++)
                #pragma unroll
                for (int nb = 0; nb < 4; nb++) {
                    mma16816(acc[mb][nb], a[mb], &bh[nb >> 1][(nb & 1) * 2]);
                    mma16816(acc[mb][nb], a[mb], &bl[nb >> 1][(nb & 1) * 2]);
                }
            #pragma unroll
            for (int mb = 0; mb < 4; mb++) {
                uint32_t off = sw128((uint32_t)((aRow + mb*16) * 128 + ks*32 + aKb));
                ldsm4(a[mb], aL + off);
            }
            #pragma unroll
            for (int mb = 0; mb < 4; mb++)
                #pragma unroll
                for (int nb = 0; nb < 4; nb++)
                    mma16816(acc[mb][nb], a[mb], &bh[nb >> 1][(nb & 1) * 2]);
        }
    }

    const int rowE = m0 + warp_m * 64 + (lane >> 2);
    const int colE = n0 + warp_n * 32 + (lane & 3) * 2;
    #pragma unroll
    for (int mb = 0; mb < 4; mb++)
        #pragma unroll
        for (int nb = 0; nb < 4; nb++) {
            float* p = C + (size_t)(rowE + mb*16) * D_ + colE + nb*8;
            *(float2*)p            = make_float2(acc[mb][nb][0], acc[mb][nb][1]);
            *(float2*)(p + 8*D_)   = make_float2(acc[mb][nb][2], acc[mb][nb][3]);
        }
}

// ---------------- HMMA flash attention: 3-stage KV pipeline ------------------
#define AQ 128
#define AK 64
#define A_KVT    8192                 // 64 rows x 128B
#define A_BUFSZ (4*A_KVT)             // 32768: Kh,Kl,Vh,Vl
#define A_SMQH  0
#define A_SMQL  16384
#define A_SMBUF 32768
#define A_SMBIAS (A_SMBUF + 3*A_BUFSZ)   // 131072
#define A_SMEM  (A_SMBIAS + 3*192*4)     // 133376

__global__ void __launch_bounds__(256, 1)
attn_mma(const __nv_bfloat16* __restrict__ Qh, const __nv_bfloat16* __restrict__ Ql,
         const __nv_bfloat16* __restrict__ Kh, const __nv_bfloat16* __restrict__ Kl,
         const __nv_bfloat16* __restrict__ Vh, const __nv_bfloat16* __restrict__ Vl,
         __nv_bfloat16* __restrict__ ctxh, __nv_bfloat16* __restrict__ ctxl) {
    extern __shared__ char dsm[];
    const uint32_t smb = smem_u32(dsm);
    float* bias_s = (float*)(dsm + A_SMBIAS);   // [3][192]

    const int tid  = threadIdx.x;
    const int lane = tid & 31;
    const int w    = tid >> 5;
    const int q0 = blockIdx.x * AQ;
    const int h  = blockIdx.y;
    const int b  = blockIdx.z;
    const int bh = b * H_ + h;

    const int aRow = w * 16 + (lane & 15);
    const int aKb  = (lane >> 4) * 16;
    const int bRowB = ((lane >> 4) << 3) + (lane & 7);
    const int bKb   = ((lane >> 3) & 1) * 16;
    const int vRow = (((lane >> 3) & 1) << 3) + (lane & 7);
    const int vKb  = (lane >> 4) * 16;

    auto prefetch = [&](int it) {
        const int k0 = it * AK;
        const uint32_t db = smb + A_SMBUF + (uint32_t)(it % 3) * A_BUFSZ;
        #pragma unroll
        for (int j = 0; j < 2; j++) {
            int ci = tid + j * 256;
            int row = ci >> 3, f4 = ci & 7;
            uint32_t so = sw128((uint32_t)(row * 128 + f4 * 16));
            size_t g = ((size_t)bh * S_ + k0 + row) * DK_ + f4 * 8;
            cp_async16(db + 0*A_KVT + so, Kh + g);
            cp_async16(db + 1*A_KVT + so, Kl + g);
            cp_async16(db + 2*A_KVT + so, Vh + g);
            cp_async16(db + 3*A_KVT + so, Vl + g);
        }
    };
    auto stage_bias = [&](int it) {
        if (tid < 191)
            bias_s[(it % 3) * 192 + tid] =
                g_bias[h * NDELTA + it * AK - q0 + tid + 896];
    };

    // group 0: Q tiles + KV0 ; group 1: KV1
    #pragma unroll
    for (int j = 0; j < 4; j++) {
        int ci = tid + j * 256;
        int row = ci >> 3, f4 = ci & 7;
        uint32_t so = sw128((uint32_t)(row * 128 + f4 * 16));
        size_t ga = ((size_t)bh * S_ + q0 + row) * DK_ + f4 * 8;
        cp_async16(smb + A_SMQH + so, Qh + ga);
        cp_async16(smb + A_SMQL + so, Ql + ga);
    }
    prefetch(0); stage_bias(0); cp_commit();
    prefetch(1); stage_bias(1); cp_commit();

    float m0r = -INFINITY, m1r = -INFINITY, l0 = 0.f, l1 = 0.f;
    float oa[8][4];
    #pragma unroll
    for (int i = 0; i < 8; i++)
        #pragma unroll
        for (int j = 0; j < 4; j++) oa[i][j] = 0.f;

    const int kcb = (lane & 3) * 2;
    const int rql = w * 16 + (lane >> 2);
    const int NIT = S_ / AK;

    for (int it = 0; it < NIT; it++) {
        if (it + 1 < NIT) cp_wait<1>(); else cp_wait<0>();
        __syncthreads();                       // single barrier per iteration
        if (it + 2 < NIT) { prefetch(it + 2); stage_bias(it + 2); cp_commit(); }

        const uint32_t base = smb + A_SMBUF + (uint32_t)(it % 3) * A_BUFSZ;
        const uint32_t kH = base, kL = base + A_KVT;
        const uint32_t vH = base + 2*A_KVT, vL = base + 3*A_KVT;
        const float* bp = bias_s + (it % 3) * 192;

        // ---- scores ----
        float sa[8][4];
        #pragma unroll
        for (int i = 0; i < 8; i++)
            #pragma unroll
            for (int j = 0; j < 4; j++) sa[i][j] = 0.f;

        #pragma unroll
        for (int ks = 0; ks < 4; ks++) {
            uint32_t qh_f[4], ql_f[4];
            uint32_t qoff = sw128((uint32_t)(aRow * 128 + ks*32 + aKb));
            ldsm4(qh_f, smb + A_SMQH + qoff);
            ldsm4(ql_f, smb + A_SMQL + qoff);
            uint32_t khf[4][4], klf[4][4];
            #pragma unroll
            for (int nb2 = 0; nb2 < 4; nb2++) {
                uint32_t off = sw128((uint32_t)((bRowB + nb2*16) * 128 + ks*32 + bKb));
                ldsm4(khf[nb2], kH + off);
                ldsm4(klf[nb2], kL + off);
            }
            #pragma unroll
            for (int t = 0; t < 8; t++) {
                uint32_t* bhp = &khf[t >> 1][(t & 1) * 2];
                uint32_t* blp = &klf[t >> 1][(t & 1) * 2];
                mma16816(sa[t], qh_f, bhp);
                mma16816(sa[t], qh_f, blp);
                mma16816(sa[t], ql_f, bhp);
            }
        }

        // ---- bias + online softmax ----
        float mx0 = -INFINITY, mx1 = -INFINITY;
        #pragma unroll
        for (int t = 0; t < 8; t++) {
            int bi = t*8 + kcb - rql + 127;
            float s0 = sa[t][0] + bp[bi];
            float s1 = sa[t][1] + bp[bi + 1];
            float s2 = sa[t][2] + bp[bi - 8];
            float s3 = sa[t][3] + bp[bi - 7];
            sa[t][0] = s0; sa[t][1] = s1; sa[t][2] = s2; sa[t][3] = s3;
            mx0 = fmaxf(mx0, fmaxf(s0, s1));
            mx1 = fmaxf(mx1, fmaxf(s2, s3));
        }
        mx0 = fmaxf(mx0, __shfl_xor_sync(0xffffffffu, mx0, 1));
        mx0 = fmaxf(mx0, __shfl_xor_sync(0xffffffffu, mx0, 2));
        mx1 = fmaxf(mx1, __shfl_xor_sync(0xffffffffu, mx1, 1));
        mx1 = fmaxf(mx1, __shfl_xor_sync(0xffffffffu, mx1, 2));
        float mn0 = fmaxf(m0r, mx0), mn1 = fmaxf(m1r, mx1);
        float c0 = __expf(m0r - mn0), c1 = __expf(m1r - mn1);
        l0 *= c0; l1 *= c1;
        #pragma unroll
        for (int dt = 0; dt < 8; dt++) {
            oa[dt][0] *= c0; oa[dt][1] *= c0;
            oa[dt][2] *= c1; oa[dt][3] *= c1;
        }
        m0r = mn0; m1r = mn1;
        #pragma unroll
        for (int t = 0; t < 8; t++) {
            float p0 = __expf(sa[t][0] - mn0);
            float p1 = __expf(sa[t][1] - mn0);
            float p2 = __expf(sa[t][2] - mn1);
            float p3 = __expf(sa[t][3] - mn1);
            l0 += p0 + p1; l1 += p2 + p3;
            sa[t][0] = p0; sa[t][1] = p1; sa[t][2] = p2; sa[t][3] = p3;
        }

        // ---- PV: V via trans-ldmatrix from [s][dk] layout ----
        #pragma unroll
        for (int ks = 0; ks < 4; ks++) {
            const int t0 = 2*ks, t1 = 2*ks + 1;
            uint32_t pah[4], pal[4];
            #pragma unroll
            for (int half = 0; half < 2; half++) {
                const int tt = half ? t1 : t0;
                float p0 = sa[tt][0], p1 = sa[tt][1], p2 = sa[tt][2], p3 = sa[tt][3];
                float h0 = bf16rt(p0), h1 = bf16rt(p1), h2 = bf16rt(p2), h3 = bf16rt(p3);
                pah[half*2 + 0] = pack_bf2(p0, p1);
                pah[half*2 + 1] = pack_bf2(p2, p3);
                pal[half*2 + 0] = pack_bf2(p0 - h0, p1 - h1);
                pal[half*2 + 1] = pack_bf2(p2 - h2, p3 - h3);
            }
            uint32_t vhf[4][4], vlf[4][4];
            #pragma unroll
            for (int nb2 = 0; nb2 < 4; nb2++) {
                uint32_t off = sw128((uint32_t)((ks*16 + vRow) * 128 + nb2*32 + vKb));
                ldsm4t(vhf[nb2], vH + off);
                ldsm4t(vlf[nb2], vL + off);
            }
            #pragma unroll
            for (int dt = 0; dt < 8; dt++) {
                uint32_t* b1 = &vhf[dt >> 1][(dt & 1) * 2];
                uint32_t* b2 = &vlf[dt >> 1][(dt & 1) * 2];
                mma16816(oa[dt], pah, b1);
                mma16816(oa[dt], pah, b2);
                mma16816(oa[dt], pal, b1);
            }
        }
    }

    // ---- finalize: ctx as bf16 hi/lo split [m][h*dk] ----
    l0 += __shfl_xor_sync(0xffffffffu, l0, 1);
    l0 += __shfl_xor_sync(0xffffffffu, l0, 2);
    l1 += __shfl_xor_sync(0xffffffffu, l1, 1);
    l1 += __shfl_xor_sync(0xffffffffu, l1, 2);
    float inv0 = 1.f / l0, inv1 = 1.f / l1;
    const int rowg = b * S_ + q0 + rql;
    #pragma unroll
    for (int dt = 0; dt < 8; dt++) {
        size_t dst = (size_t)rowg * D_ + h * DK_ + dt*8 + kcb;
        float v0 = oa[dt][0] * inv0, v1 = oa[dt][1] * inv0;
        float v2 = oa[dt][2] * inv1, v3 = oa[dt][3] * inv1;
        float h0 = bf16rt(v0), h1 = bf16rt(v1), h2 = bf16rt(v2), h3 = bf16rt(v3);
        *(uint32_t*)(ctxh + dst)          = pack_bf2(v0, v1);
        *(uint32_t*)(ctxl + dst)          = pack_bf2(v0 - h0, v1 - h1);
        *(uint32_t*)(ctxh + dst + 8*D_)   = pack_bf2(v2, v3);
        *(uint32_t*)(ctxl + dst + 8*D_)   = pack_bf2(v2 - h2, v3 - h3);
    }
}

// ---------------- launch -----------------------------------------------------
extern "C" void kernel_launch(void* const* d_in, const int* in_sizes, int n_in,
                              void* d_out, int out_size) {
    const float* x   = (const float*)d_in[0];
    const float* Wq  = (const float*)d_in[1];
    const float* Wk  = (const float*)d_in[2];
    const float* Wv  = (const float*)d_in[3];
    const float* Wo  = (const float*)d_in[4];
    const float* rel = (const float*)d_in[5];
    float* out = (float*)d_out;

    __nv_bfloat16 *xh, *xl, *chh, *cll, *wh, *wl;
    cudaGetSymbolAddress((void**)&xh, g_xh);
    cudaGetSymbolAddress((void**)&xl, g_xl);
    cudaGetSymbolAddress((void**)&chh, g_ch);
    cudaGetSymbolAddress((void**)&cll, g_cl);
    cudaGetSymbolAddress((void**)&wh, g_wh);
    cudaGetSymbolAddress((void**)&wl, g_wl);
    __nv_bfloat16 *aqh, *aql, *akh, *akl, *avh, *avl;
    cudaGetSymbolAddress((void**)&aqh, g_aqh);
    cudaGetSymbolAddress((void**)&aql, g_aql);
    cudaGetSymbolAddress((void**)&akh, g_akh);
    cudaGetSymbolAddress((void**)&akl, g_akl);
    cudaGetSymbolAddress((void**)&avh, g_avh);
    cudaGetSymbolAddress((void**)&avl, g_avl);

    cudaFuncSetAttribute(qkv_gemm,    cudaFuncAttributeMaxDynamicSharedMemorySize, GSMEM);
    cudaFuncSetAttribute(gemm_bf16x3, cudaFuncAttributeMaxDynamicSharedMemorySize, GSMEM);
    cudaFuncSetAttribute(attn_mma,    cudaFuncAttributeMaxDynamicSharedMemorySize, A_SMEM);

    bias_kernel<<<(NDELTA + 127) / 128, 128>>>(rel);

    split_act<<<(M_ * D_ / 4) / 256, 256>>>((const float4*)x, xh, xl);
    {
        dim3 gt(32, 32, 4), bt(32, 8);
        split_wT<<<gt, bt>>>(Wq, Wk, Wv, Wo, wh, wl);
    }

    dim3 gq(24, 64);             // 3 weight mats x 8 n-tiles, 64 m-tiles
    qkv_gemm<<<gq, 256, GSMEM>>>(xh, xl, wh, wl, aqh, aql, akh, akl, avh, avl);

    dim3 ga(S_ / AQ, H_, B_);    // (8, 16, 8)
    attn_mma<<<ga, 256, A_SMEM>>>(aqh, aql, akh, akl, avh, avl, chh, cll);

    dim3 gg(D_ / GN, M_ / GM);   // (8, 64)
    gemm_bf16x3<<<gg, 256, GSMEM>>>(chh, cll, wh + 3*(size_t)D_*D_, wl + 3*(size_t)D_*D_, out);
}